// round 13
// baseline (speedup 1.0000x reference)
#include <cuda_runtime.h>
#include <cuda_bf16.h>
#include <math_constants.h>
#include <cstdint>

#define B_   4
#define S_   2048
#define D_   256
#define H_   8
#define HD_  32
#define KEEP 204            // int(2048 * 0.1)
#define KPAD 208            // padded keys in global V^T layout
#define ROWS (B_ * S_)      // 8192
#define KV_ROWS (B_ * KEEP) // 816
#define KD   256

// ------------------------- scratch (static device globals) -------------------
__device__ float g_importance[ROWS];
__device__ int   g_rowmap[KV_ROWS];
__device__ int   g_kvready;                 // topk completion counter
__device__ __nv_bfloat16 g_xhi[ROWS * D_],   g_xlo[ROWS * D_];
__device__ __nv_bfloat16 g_winhi[3 * D_ * D_], g_winlo[3 * D_ * D_];
__device__ __nv_bfloat16 g_wouthi[D_ * D_],  g_woutlo[D_ * D_];
__device__ __nv_bfloat16 g_qhi[ROWS * D_],   g_qlo[ROWS * D_];      // Q * log2e/sqrt(hd)
__device__ __nv_bfloat16 g_khi[KV_ROWS * D_], g_klo[KV_ROWS * D_];
__device__ __nv_bfloat16 g_vthi[B_ * H_ * HD_ * KPAD], g_vtlo[B_ * H_ * HD_ * KPAD];
__device__ __nv_bfloat16 g_athi[ROWS * D_],  g_atlo[ROWS * D_];

// ========================= helpers ============================================
__device__ __forceinline__ uint32_t smem_u32(const void* p) {
    uint32_t a;
    asm("{ .reg .u64 t; cvta.to.shared.u64 t, %1; cvt.u32.u64 %0, t; }" : "=r"(a) : "l"(p));
    return a;
}
__device__ __forceinline__ void ldsm_x4(uint32_t& r0, uint32_t& r1, uint32_t& r2,
                                        uint32_t& r3, uint32_t addr) {
    asm volatile("ldmatrix.sync.aligned.m8n8.x4.shared.b16 {%0,%1,%2,%3}, [%4];"
                 : "=r"(r0), "=r"(r1), "=r"(r2), "=r"(r3) : "r"(addr));
}
__device__ __forceinline__ void mma_bf16(float* c, const uint32_t* a, const uint32_t* b) {
    asm volatile("mma.sync.aligned.m16n8k16.row.col.f32.bf16.bf16.f32 "
                 "{%0,%1,%2,%3}, {%4,%5,%6,%7}, {%8,%9}, {%0,%1,%2,%3};"
                 : "+f"(c[0]), "+f"(c[1]), "+f"(c[2]), "+f"(c[3])
                 : "r"(a[0]), "r"(a[1]), "r"(a[2]), "r"(a[3]), "r"(b[0]), "r"(b[1]));
}
#define CP16(dst, src) \
    asm volatile("cp.async.cg.shared.global [%0], [%1], 16;" :: "r"(dst), "l"(src))
#define CP_COMMIT() asm volatile("cp.async.commit_group;" ::: "memory")
#define CP_WAIT(n)  asm volatile("cp.async.wait_group %0;" :: "n"(n) : "memory")

__device__ __forceinline__ void split_bf16(float v, __nv_bfloat16& h, __nv_bfloat16& l) {
    h = __float2bfloat16(v);
    l = __float2bfloat16(v - __bfloat162float(h));
}
__device__ __forceinline__ void pack_hi_lo(float a, float b, uint32_t& hi, uint32_t& lo) {
    __nv_bfloat16 ha, la, hb, lb;
    split_bf16(a, ha, la); split_bf16(b, hb, lb);
    __nv_bfloat162 th = __halves2bfloat162(ha, hb);
    __nv_bfloat162 tl = __halves2bfloat162(la, lb);
    hi = *(uint32_t*)&th; lo = *(uint32_t*)&tl;
}
// 2^x via FMA pipe (no MUFU): magic rounding + degree-5 poly, rel err < 3e-6
__device__ __forceinline__ float exp2_fast(float x) {
    x = fmaxf(x, -120.f);
    float t = x + 12582912.f;
    float f = x - (t - 12582912.f);
    uint32_t ti = __float_as_uint(t);
    float s = __uint_as_float((ti << 23) + 0x3F800000u);
    float p = 1.33335581e-3f;
    p = fmaf(p, f, 9.61812911e-3f);
    p = fmaf(p, f, 5.55041087e-2f);
    p = fmaf(p, f, 2.40226507e-1f);
    p = fmaf(p, f, 6.93147181e-1f);
    p = fmaf(p, f, 1.0f);
    return p * s;
}

// ========================= bf16x3 GEMM body (64x64 tile, 3-stage) =============
#define GKP 80
#define G_AHI 0
#define G_ALO 5120
#define G_BHI 10240
#define G_BLO 15360
#define G_STAGE 20480
#define SMEM_GM (3 * G_STAGE)                    // 61440 B

__device__ __forceinline__ void gemm_body(
    int bx, int by, char* smem,
    const __nv_bfloat16* __restrict__ Ahi, const __nv_bfloat16* __restrict__ Alo,
    const int* __restrict__ rowmap,
    const __nv_bfloat16* __restrict__ Bhi, const __nv_bfloat16* __restrict__ Blo,
    const float* __restrict__ bias, int M, int N, int mode, float scale,
    float* __restrict__ Cf, __nv_bfloat16* __restrict__ Chi, __nv_bfloat16* __restrict__ Clo,
    __nv_bfloat16* __restrict__ VThi, __nv_bfloat16* __restrict__ VTlo) {
    uint32_t sb = smem_u32(smem);
    int tid = threadIdx.x, wid = tid >> 5, lane = tid & 31;
    int rowBase = by * 64, colBase = bx * 64;
    int warp_m = (wid >> 2) * 32;
    int warp_n = (wid & 3) * 16;

    int ra = tid >> 2, ca = tid & 3;
    int gar = (rowBase + ra < M) ? (rowmap ? rowmap[rowBase + ra] : rowBase + ra) : 0;
    const __nv_bfloat16* sAh = Ahi + (size_t)gar * KD + ca * 8;
    const __nv_bfloat16* sAl = Alo + (size_t)gar * KD + ca * 8;
    const __nv_bfloat16* sBh = Bhi + (size_t)(colBase + ra) * KD + ca * 8;
    const __nv_bfloat16* sBl = Blo + (size_t)(colBase + ra) * KD + ca * 8;
    uint32_t dd = sb + (uint32_t)(ra * GKP + ca * 16);

    auto issue = [&](int kt, int st) {
        uint32_t so = (uint32_t)st * G_STAGE;
        int ko = kt * 32;
        CP16(dd + so + G_AHI, sAh + ko);
        CP16(dd + so + G_ALO, sAl + ko);
        CP16(dd + so + G_BHI, sBh + ko);
        CP16(dd + so + G_BLO, sBl + ko);
        CP_COMMIT();
    };

    uint32_t arel[2];
    #pragma unroll
    for (int mf = 0; mf < 2; mf++)
        arel[mf] = (uint32_t)((warp_m + mf * 16 + (lane & 15)) * GKP + (lane >> 4) * 16);
    int bg = lane >> 3, br = lane & 7;
    uint32_t brel = (uint32_t)((warp_n + (bg >> 1) * 8 + br) * GKP + (bg & 1) * 16);

    float acc[2][2][4] = {};

    issue(0, 0);
    issue(1, 1);
    #pragma unroll 1
    for (int kt = 0; kt < 8; kt++) {
        CP_WAIT(1);
        __syncthreads();
        if (kt < 6) issue(kt + 2, (kt + 2) % 3);
        uint32_t base = sb + (uint32_t)((kt % 3) * G_STAGE);
        #pragma unroll
        for (int kc = 0; kc < 2; kc++) {
            uint32_t koff = (uint32_t)kc * 32;
            uint32_t bh[2][2], bl[2][2];
            ldsm_x4(bh[0][0], bh[0][1], bh[1][0], bh[1][1], base + G_BHI + brel + koff);
            ldsm_x4(bl[0][0], bl[0][1], bl[1][0], bl[1][1], base + G_BLO + brel + koff);
            #pragma unroll
            for (int mf = 0; mf < 2; mf++) {
                uint32_t ah[4], al[4];
                ldsm_x4(ah[0], ah[1], ah[2], ah[3], base + G_AHI + arel[mf] + koff);
                ldsm_x4(al[0], al[1], al[2], al[3], base + G_ALO + arel[mf] + koff);
                #pragma unroll
                for (int nf = 0; nf < 2; nf++) {
                    mma_bf16(acc[mf][nf], ah, bh[nf]);
                    mma_bf16(acc[mf][nf], ah, bl[nf]);
                    mma_bf16(acc[mf][nf], al, bh[nf]);
                }
            }
        }
    }

    #pragma unroll
    for (int mf = 0; mf < 2; mf++) {
        #pragma unroll
        for (int nf = 0; nf < 2; nf++) {
            int n = colBase + warp_n + nf * 8 + (lane & 3) * 2;
            float b0 = __ldg(bias + n), b1 = __ldg(bias + n + 1);
            #pragma unroll
            for (int half = 0; half < 2; half++) {
                int m = rowBase + warp_m + mf * 16 + (lane >> 2) + half * 8;
                if (m >= M) continue;
                float o0 = acc[mf][nf][half * 2 + 0] + b0;
                float o1 = acc[mf][nf][half * 2 + 1] + b1;
                if (mode == 0) {
                    *(float2*)(Cf + (size_t)m * N + n) = make_float2(o0, o1);
                } else if (mode == 1) {
                    o0 *= scale; o1 *= scale;
                    __nv_bfloat16 h0, l0, h1, l1;
                    split_bf16(o0, h0, l0); split_bf16(o1, h1, l1);
                    *(__nv_bfloat162*)(Chi + (size_t)m * N + n) = __halves2bfloat162(h0, h1);
                    *(__nv_bfloat162*)(Clo + (size_t)m * N + n) = __halves2bfloat162(l0, l1);
                } else {
                    __nv_bfloat16 h0, l0, h1, l1;
                    split_bf16(o0, h0, l0); split_bf16(o1, h1, l1);
                    if (n < 256) {
                        *(__nv_bfloat162*)(Chi + (size_t)m * 256 + n) = __halves2bfloat162(h0, h1);
                        *(__nv_bfloat162*)(Clo + (size_t)m * 256 + n) = __halves2bfloat162(l0, l1);
                    } else {
                        int bb = m / KEEP, j = m - bb * KEEP;
                        int hh = (n - 256) >> 5, dd2 = (n - 256) & 31;
                        size_t i0 = ((size_t)(bb * H_ + hh) * HD_ + dd2) * KPAD + j;
                        size_t i1 = ((size_t)(bb * H_ + hh) * HD_ + dd2 + 1) * KPAD + j;
                        VThi[i0] = h0; VTlo[i0] = l0;
                        VThi[i1] = h1; VTlo[i1] = l1;
                    }
                }
            }
        }
    }
}

// ========================= launch 1: gate GEMM || convert ====================
#define CN1 (ROWS * D_ / 4)
#define CN2 (3 * D_ * D_ / 4)
#define CN3 (D_ * D_ / 4)
#define GATE_BLOCKS (ROWS / 64)     // 128
#define CONV_BLOCKS ((CN1 + CN2 + CN3) / 256)   // 2304

__global__ __launch_bounds__(256) void k_gate_convert(
    const float* __restrict__ x, const float* __restrict__ gw1,
    const float* __restrict__ gb1, const float* __restrict__ gw2,
    const float* __restrict__ gb2,
    const float* __restrict__ w_in, const float* __restrict__ w_out) {
    __shared__ float As[16][68];
    __shared__ float Ws[16][68];
    int tid = threadIdx.x;
    if (blockIdx.x == 0 && tid == 0) g_kvready = 0;   // reset for this graph replay
    if (blockIdx.x >= GATE_BLOCKS) {
        int i = (blockIdx.x - GATE_BLOCKS) * 256 + tid;
        const float4* src;
        __nv_bfloat162 *hi, *lo;
        int off;
        if (i < CN1) {
            src = (const float4*)x; hi = (__nv_bfloat162*)g_xhi; lo = (__nv_bfloat162*)g_xlo; off = i;
        } else if (i < CN1 + CN2) {
            src = (const float4*)w_in; hi = (__nv_bfloat162*)g_winhi; lo = (__nv_bfloat162*)g_winlo;
            off = i - CN1;
        } else {
            src = (const float4*)w_out; hi = (__nv_bfloat162*)g_wouthi; lo = (__nv_bfloat162*)g_woutlo;
            off = i - CN1 - CN2;
        }
        float4 v = src[off];
        __nv_bfloat16 hx, hy, hz, hw, lx, ly, lz, lw;
        split_bf16(v.x, hx, lx); split_bf16(v.y, hy, ly);
        split_bf16(v.z, hz, lz); split_bf16(v.w, hw, lw);
        hi[2*off]   = __halves2bfloat162(hx, hy);
        hi[2*off+1] = __halves2bfloat162(hz, hw);
        lo[2*off]   = __halves2bfloat162(lx, ly);
        lo[2*off+1] = __halves2bfloat162(lz, lw);
        return;
    }
    int rowBase = blockIdx.x * 64;
    int ar = tid & 63, ac = (tid >> 6) * 4;
    const float* asrc = x + (size_t)(rowBase + ar) * KD + ac;
    const float* wsrc = gw1 + (size_t)ar * KD + ac;
    float4 a0 = *(const float4*)asrc;
    float4 w0 = *(const float4*)wsrc;
    int tx = tid & 15, ty = tid >> 4;
    float acc[4][4] = {};
    for (int k0 = 0; k0 < KD; k0 += 16) {
        As[ac+0][ar]=a0.x; As[ac+1][ar]=a0.y; As[ac+2][ar]=a0.z; As[ac+3][ar]=a0.w;
        Ws[ac+0][ar]=w0.x; Ws[ac+1][ar]=w0.y; Ws[ac+2][ar]=w0.z; Ws[ac+3][ar]=w0.w;
        __syncthreads();
        if (k0 + 16 < KD) {
            a0 = *(const float4*)(asrc + k0 + 16);
            w0 = *(const float4*)(wsrc + k0 + 16);
        }
        #pragma unroll
        for (int kk = 0; kk < 16; kk++) {
            float a[4], w[4];
            *(float4*)a = *(const float4*)&As[kk][ty * 4];
            *(float4*)w = *(const float4*)&Ws[kk][tx * 4];
            #pragma unroll
            for (int i = 0; i < 4; i++)
                #pragma unroll
                for (int j = 0; j < 4; j++)
                    acc[i][j] = fmaf(a[i], w[j], acc[i][j]);
        }
        __syncthreads();
    }
    float b1v[4], w2v[4];
    #pragma unroll
    for (int j = 0; j < 4; j++) {
        b1v[j] = gb1[tx * 4 + j];
        w2v[j] = gw2[tx * 4 + j];
    }
    float bb2 = gb2[0];
    #pragma unroll
    for (int i = 0; i < 4; i++) {
        float part = 0.f;
        #pragma unroll
        for (int j = 0; j < 4; j++)
            part += fmaxf(acc[i][j] + b1v[j], 0.f) * w2v[j];
        part += __shfl_xor_sync(0xffffffffu, part, 1);
        part += __shfl_xor_sync(0xffffffffu, part, 2);
        part += __shfl_xor_sync(0xffffffffu, part, 4);
        part += __shfl_xor_sync(0xffffffffu, part, 8);
        if (tx == 0)
            g_importance[rowBase + ty * 4 + i] = 1.f / (1.f + expf(-(part + bb2)));
    }
}

// ========================= launch 2: topk + Q GEMM + KV GEMM (fused) =========
__device__ void topk_body(int b, char* smem) {
    uint32_t* bits = (uint32_t*)smem;
    int* hist   = (int*)(smem + 8192);
    int* eqlist = (int*)(smem + 9216);
    int* sc     = (int*)(smem + 10240);
    int t = threadIdx.x;
    for (int i = t; i < S_; i += 256)
        bits[i] = __float_as_uint(g_importance[b * S_ + i]);
    __syncthreads();

    uint32_t prefix = 0, prefmask = 0;
    int k_rem = KEEP;
    #pragma unroll
    for (int lev = 0; lev < 4; lev++) {
        int shift = 24 - lev * 8;
        hist[t] = 0;
        __syncthreads();
        for (int i = t; i < S_; i += 256) {
            uint32_t v = bits[i];
            if ((v & prefmask) == prefix) atomicAdd(&hist[(v >> shift) & 255], 1);
        }
        __syncthreads();
        if (t == 0) {
            int acc = 0, bin = 255;
            for (; bin > 0; bin--) {
                if (acc + hist[bin] >= k_rem) break;
                acc += hist[bin];
            }
            sc[0] = bin; sc[1] = acc;
        }
        __syncthreads();
        prefix |= ((uint32_t)sc[0]) << shift;
        prefmask |= (0xFFu << shift);
        k_rem -= sc[1];
        __syncthreads();
    }
    if (t == 0) { sc[2] = 0; sc[3] = 0; }
    __syncthreads();
    for (int i = t; i < S_; i += 256) {
        uint32_t v = bits[i];
        if (v > prefix) {
            int s = atomicAdd(&sc[2], 1);
            g_rowmap[b * KEEP + s] = b * S_ + i;
        } else if (v == prefix) {
            int s = atomicAdd(&sc[3], 1);
            if (s < 256) eqlist[s] = i;
        }
    }
    __syncthreads();
    int ne = min(sc[3], 256);
    if (t < ne) {
        int idx = eqlist[t], rank = 0;
        for (int j = 0; j < ne; j++) rank += (eqlist[j] < idx);
        if (rank < k_rem) g_rowmap[b * KEEP + sc[2] + rank] = b * S_ + idx;
    }
    // signal completion (release)
    __syncthreads();
    __threadfence();
    if (t == 0) atomicAdd(&g_kvready, 1);
}

#define QG_BLOCKS (4 * (ROWS / 64))   // 512
#define KV_BLOCKS (8 * 13)            // 104

__global__ __launch_bounds__(256) void k_fused_mid(
    const float* __restrict__ b_in, float qscale) {
    extern __shared__ char smem[];
    if (blockIdx.x < B_) {                       // topk: wave-1 resident
        topk_body(blockIdx.x, smem);
        return;
    }
    if (blockIdx.x < B_ + QG_BLOCKS) {           // Q projection
        int g = blockIdx.x - B_;
        gemm_body(g & 3, g >> 2, smem,
                  g_xhi, g_xlo, nullptr, g_winhi, g_winlo,
                  b_in, ROWS, D_, 1, qscale,
                  nullptr, g_qhi, g_qlo, nullptr, nullptr);
        return;
    }
    // KV projection: wait for all 4 topk blocks (scheduled in wave 1;
    // KV block ids >= 516 start at wave >= 2, so no deadlock)
    if (threadIdx.x == 0) {
        while (*(volatile int*)&g_kvready < B_) {}
    }
    __syncthreads();
    __threadfence();   // acquire: rowmap visible
    int g = blockIdx.x - B_ - QG_BLOCKS;
    gemm_body(g & 7, g >> 3, smem,
              g_xhi, g_xlo, g_rowmap,
              g_winhi + D_ * D_, g_winlo + D_ * D_,
              b_in + D_, KV_ROWS, 2 * D_, 2, 1.f,
              nullptr, g_khi, g_klo, g_vthi, g_vtlo);
}

// ========================= launch 4: out-proj GEMM ===========================
__global__ __launch_bounds__(256) void k_outgemm(
    const float* __restrict__ b_out, float* __restrict__ out) {
    extern __shared__ char smem[];
    gemm_body(blockIdx.x, blockIdx.y, smem,
              g_athi, g_atlo, nullptr, g_wouthi, g_woutlo,
              b_out, ROWS, D_, 0, 1.f,
              out, nullptr, nullptr, nullptr, nullptr);
}

// ========================= launch 3: MMA attention (key-chunked) =============
#define PVS2 240
#define C_KHI 0
#define C_KLO 8960
#define C_VHI 17920
#define C_VLO (C_VHI + HD_ * PVS2)
#define SMEM_AT2 (C_VLO + HD_ * PVS2)      // 33280

__global__ __launch_bounds__(128, 4) void attn_mma() {
    extern __shared__ char smem[];
    uint32_t sb = smem_u32(smem);
    int tid = threadIdx.x, wid = tid >> 5, lane = tid & 31;
    int b = blockIdx.x >> 3, h = blockIdx.x & 7;
    int qbase = blockIdx.y * 64;
    int warp_m = wid * 16;
    int bg = lane >> 3, br = lane & 7;

    int qrow = qbase + warp_m + (lane >> 2);
    size_t q0 = (size_t)(b * S_ + qrow) * D_ + h * HD_ + (lane & 3) * 2;
    size_t q1 = q0 + 8 * (size_t)D_;
    uint32_t aqh[2][4], aql[2][4];
    #pragma unroll
    for (int ks = 0; ks < 2; ks++) {
        aqh[ks][0] = *(const uint32_t*)(g_qhi + q0 + ks * 16);
        aqh[ks][1] = *(const uint32_t*)(g_qhi + q1 + ks * 16);
        aqh[ks][2] = *(const uint32_t*)(g_qhi + q0 + 8 + ks * 16);
        aqh[ks][3] = *(const uint32_t*)(g_qhi + q1 + 8 + ks * 16);
        aql[ks][0] = *(const uint32_t*)(g_qlo + q0 + ks * 16);
        aql[ks][1] = *(const uint32_t*)(g_qlo + q1 + ks * 16);
        aql[ks][2] = *(const uint32_t*)(g_qlo + q0 + 8 + ks * 16);
        aql[ks][3] = *(const uint32_t*)(g_qlo + q1 + 8 + ks * 16);
    }

    uint32_t pbr0 = (uint32_t)(((bg >> 1) * 8 + br) * PVS2 + (bg & 1) * 16);
    uint32_t pbr1 = pbr0 + 16 * PVS2;

    float m0, m1, sum0 = 0.f, sum1 = 0.f;
    float oacc[4][4] = {};

    #pragma unroll
    for (int ch = 0; ch < 2; ch++) {
        int kb = ch * 112;
        if (ch) __syncthreads();
        for (int i = tid; i < 112 * 4; i += 128) {
            int j = i >> 2, c = i & 3;
            int gk = kb + j;
            uint4 vh = make_uint4(0, 0, 0, 0), vl = vh;
            if (gk < KEEP) {
                size_t off = (size_t)(b * KEEP + gk) * D_ + h * HD_ + c * 8;
                vh = *(const uint4*)(g_khi + off);
                vl = *(const uint4*)(g_klo + off);
            }
            *(uint4*)(smem + C_KHI + j * 80 + c * 16) = vh;
            *(uint4*)(smem + C_KLO + j * 80 + c * 16) = vl;
        }
        {
            int d = tid >> 2;
            size_t rowoff = ((size_t)(b * H_ + h) * HD_ + d) * KPAD + kb;
            for (int c = tid & 3; c < 14; c += 4) {
                int gkey = kb + c * 8;
                uint4 vh, vl;
                if (gkey + 8 <= KEEP) {
                    vh = *(const uint4*)(g_vthi + rowoff + c * 8);
                    vl = *(const uint4*)(g_vtlo + rowoff + c * 8);
                } else if (gkey < KEEP) {
                    uint2 th = *(const uint2*)(g_vthi + rowoff + c * 8);
                    uint2 tl = *(const uint2*)(g_vtlo + rowoff + c * 8);
                    vh = make_uint4(th.x, th.y, 0, 0);
                    vl = make_uint4(tl.x, tl.y, 0, 0);
                } else {
                    vh = make_uint4(0, 0, 0, 0); vl = vh;
                }
                *(uint4*)(smem + C_VHI + d * PVS2 + c * 16) = vh;
                *(uint4*)(smem + C_VLO + d * PVS2 + c * 16) = vl;
            }
        }
        __syncthreads();

        float sacc[14][4];
        #pragma unroll
        for (int t = 0; t < 14; t++)
            #pragma unroll
            for (int j = 0; j < 4; j++) sacc[t][j] = 0.f;

        #pragma unroll
        for (int nc = 0; nc < 7; nc++) {
            uint32_t brel = (uint32_t)((nc * 16 + (bg >> 1) * 8 + br) * 80 + (bg & 1) * 16);
            #pragma unroll
            for (int ks = 0; ks < 2; ks++) {
                uint32_t bh[2][2], bl[2][2];
                ldsm_x4(bh[0][0], bh[0][1], bh[1][0], bh[1][1], sb + C_KHI + brel + ks * 32);
                ldsm_x4(bl[0][0], bl[0][1], bl[1][0], bl[1][1], sb + C_KLO + brel + ks * 32);
                #pragma unroll
                for (int nf = 0; nf < 2; nf++) {
                    mma_bf16(sacc[nc * 2 + nf], aqh[ks], bh[nf]);
                    mma_bf16(sacc[nc * 2 + nf], aql[ks], bh[nf]);
                    mma_bf16(sacc[nc * 2 + nf], aqh[ks], bl[nf]);
                }
            }
        }

        if (ch == 1) {
            if ((lane & 3) >= 2) {
                sacc[11][0] = -1e30f; sacc[11][1] = -1e30f;
                sacc[11][2] = -1e30f; sacc[11][3] = -1e30f;
            }
            #pragma unroll
            for (int t = 12; t < 14; t++) {
                sacc[t][0] = -1e30f; sacc[t][1] = -1e30f;
                sacc[t][2] = -1e30f; sacc[t][3] = -1e30f;
            }
        }

        float cx0 = -1e30f, cx1 = -1e30f;
        #pragma unroll
        for (int t = 0; t < 14; t++) {
            cx0 = fmaxf(cx0, fmaxf(sacc[t][0], sacc[t][1]));
            cx1 = fmaxf(cx1, fmaxf(sacc[t][2], sacc[t][3]));
        }
        cx0 = fmaxf(cx0, __shfl_xor_sync(0xffffffffu, cx0, 1));
        cx0 = fmaxf(cx0, __shfl_xor_sync(0xffffffffu, cx0, 2));
        cx1 = fmaxf(cx1, __shfl_xor_sync(0xffffffffu, cx1, 1));
        cx1 = fmaxf(cx1, __shfl_xor_sync(0xffffffffu, cx1, 2));
        if (ch == 0) {
            m0 = cx0; m1 = cx1;
        } else {
            float nm0 = fmaxf(m0, cx0), nm1 = fmaxf(m1, cx1);
            float c0 = exp2_fast(m0 - nm0), c1 = exp2_fast(m1 - nm1);
            sum0 *= c0; sum1 *= c1;
            #pragma unroll
            for (int nf = 0; nf < 4; nf++) {
                oacc[nf][0] *= c0; oacc[nf][1] *= c0;
                oacc[nf][2] *= c1; oacc[nf][3] *= c1;
            }
            m0 = nm0; m1 = nm1;
        }

        #pragma unroll
        for (int t = 0; t < 14; t++) {
            sacc[t][0] = exp2_fast(sacc[t][0] - m0); sum0 += sacc[t][0];
            sacc[t][1] = exp2_fast(sacc[t][1] - m0); sum0 += sacc[t][1];
            sacc[t][2] = exp2_fast(sacc[t][2] - m1); sum1 += sacc[t][2];
            sacc[t][3] = exp2_fast(sacc[t][3] - m1); sum1 += sacc[t][3];
        }

        #pragma unroll
        for (int ks = 0; ks < 7; ks++) {
            uint32_t ph[4], pl[4];
            pack_hi_lo(sacc[2*ks][0],   sacc[2*ks][1],   ph[0], pl[0]);
            pack_hi_lo(sacc[2*ks][2],   sacc[2*ks][3],   ph[1], pl[1]);
            pack_hi_lo(sacc[2*ks+1][0], sacc[2*ks+1][1], ph[2], pl[2]);
            pack_hi_lo(sacc[2*ks+1][2], sacc[2*ks+1][3], ph[3], pl[3]);
            uint32_t koff = (uint32_t)ks * 32;
            uint32_t vh[4][2], vl[4][2];
            ldsm_x4(vh[0][0], vh[0][1], vh[1][0], vh[1][1], sb + C_VHI + pbr0 + koff);
            ldsm_x4(vh[2][0], vh[2][1], vh[3][0], vh[3][1], sb + C_VHI + pbr1 + koff);
            ldsm_x4(vl[0][0], vl[0][1], vl[1][0], vl[1][1], sb + C_VLO + pbr0 + koff);
            ldsm_x4(vl[2][0], vl[2][1], vl[3][0], vl[3][1], sb + C_VLO + pbr1 + koff);
            #pragma unroll
            for (int nf = 0; nf < 4; nf++) {
                mma_bf16(oacc[nf], ph, vh[nf]);
                mma_bf16(oacc[nf], pl, vh[nf]);
                mma_bf16(oacc[nf], ph, vl[nf]);
            }
        }
    }

    sum0 += __shfl_xor_sync(0xffffffffu, sum0, 1);
    sum0 += __shfl_xor_sync(0xffffffffu, sum0, 2);
    sum1 += __shfl_xor_sync(0xffffffffu, sum1, 1);
    sum1 += __shfl_xor_sync(0xffffffffu, sum1, 2);
    float inv0 = 1.f / sum0, inv1 = 1.f / sum1;

    #pragma unroll
    for (int nf = 0; nf < 4; nf++) {
        int col = h * HD_ + nf * 8 + (lane & 3) * 2;
        #pragma unroll
        for (int half = 0; half < 2; half++) {
            int row = warp_m + (lane >> 2) + half * 8;
            float il = half ? inv1 : inv0;
            float o0 = oacc[nf][half * 2 + 0] * il;
            float o1 = oacc[nf][half * 2 + 1] * il;
            __nv_bfloat16 h0, l0, h1, l1;
            split_bf16(o0, h0, l0); split_bf16(o1, h1, l1);
            size_t m = (size_t)(b * S_ + qbase + row) * D_ + col;
            *(__nv_bfloat162*)(g_athi + m) = __halves2bfloat162(h0, h1);
            *(__nv_bfloat162*)(g_atlo + m) = __halves2bfloat162(l0, l1);
        }
    }
}

// ------------------------- host launch ---------------------------------------
extern "C" void kernel_launch(void* const* d_in, const int* in_sizes, int n_in,
                              void* d_out, int out_size) {
    const float* x       = (const float*)d_in[0];
    const float* w_in    = (const float*)d_in[1];
    const float* b_in    = (const float*)d_in[2];
    const float* w_out   = (const float*)d_in[3];
    const float* b_out   = (const float*)d_in[4];
    const float* gate_w1 = (const float*)d_in[5];
    const float* gate_b1 = (const float*)d_in[6];
    const float* gate_w2 = (const float*)d_in[7];
    const float* gate_b2 = (const float*)d_in[8];
    float* out = (float*)d_out;

    cudaFuncSetAttribute(k_fused_mid, cudaFuncAttributeMaxDynamicSharedMemorySize, SMEM_GM);
    cudaFuncSetAttribute(k_outgemm, cudaFuncAttributeMaxDynamicSharedMemorySize, SMEM_GM);
    cudaFuncSetAttribute(attn_mma, cudaFuncAttributeMaxDynamicSharedMemorySize, SMEM_AT2);

    // scale = log2(e) / sqrt(32): scores come out of QK^T in log2 domain
    const float qscale = 1.4426950408889634f * 0.17677669529663687f;

    // 1. gate (exact fp32) || fp32->bf16 hi/lo conversions (+ flag reset)
    k_gate_convert<<<GATE_BLOCKS + CONV_BLOCKS, 256>>>(
        x, gate_w1, gate_b1, gate_w2, gate_b2, w_in, w_out);

    // 2. topk (4) + Q GEMM (512) + KV GEMM (104, flag-guarded) in ONE launch
    k_fused_mid<<<B_ + QG_BLOCKS + KV_BLOCKS, 256, SMEM_GM>>>(b_in, qscale);

    // 3. attention: key-chunked online softmax, 4 CTAs/SM
    attn_mma<<<dim3(B_ * H_, S_ / 64), 128, SMEM_AT2>>>();

    // 4. out projection (fp32 out)
    k_outgemm<<<dim3(D_ / 64, ROWS / 64), 256, SMEM_GM>>>(b_out, out);
}

// round 14
// speedup vs baseline: 1.1274x; 1.1274x over previous
#include <cuda_runtime.h>
#include <cuda_bf16.h>
#include <math_constants.h>
#include <cstdint>

#define B_   4
#define S_   2048
#define D_   256
#define H_   8
#define HD_  32
#define KEEP 204            // int(2048 * 0.1)
#define KPAD 208            // padded keys in global V^T layout
#define ROWS (B_ * S_)      // 8192
#define KV_ROWS (B_ * KEEP) // 816
#define KD   256

// ------------------------- scratch (static device globals) -------------------
__device__ float g_importance[ROWS];
__device__ int   g_rowmap[KV_ROWS];
__device__ __nv_bfloat16 g_xhi[ROWS * D_],   g_xlo[ROWS * D_];
__device__ __nv_bfloat16 g_winhi[3 * D_ * D_], g_winlo[3 * D_ * D_];
__device__ __nv_bfloat16 g_wouthi[D_ * D_],  g_woutlo[D_ * D_];
__device__ __nv_bfloat16 g_gw1hi[64 * D_],   g_gw1lo[64 * D_];
__device__ __nv_bfloat16 g_qhi[ROWS * D_],   g_qlo[ROWS * D_];      // Q * log2e/sqrt(hd)
__device__ __nv_bfloat16 g_khi[KV_ROWS * D_], g_klo[KV_ROWS * D_];
__device__ __nv_bfloat16 g_vthi[B_ * H_ * HD_ * KPAD], g_vtlo[B_ * H_ * HD_ * KPAD];
__device__ __nv_bfloat16 g_athi[ROWS * D_],  g_atlo[ROWS * D_];

// ========================= helpers ============================================
__device__ __forceinline__ uint32_t smem_u32(const void* p) {
    uint32_t a;
    asm("{ .reg .u64 t; cvta.to.shared.u64 t, %1; cvt.u32.u64 %0, t; }" : "=r"(a) : "l"(p));
    return a;
}
__device__ __forceinline__ void ldsm_x4(uint32_t& r0, uint32_t& r1, uint32_t& r2,
                                        uint32_t& r3, uint32_t addr) {
    asm volatile("ldmatrix.sync.aligned.m8n8.x4.shared.b16 {%0,%1,%2,%3}, [%4];"
                 : "=r"(r0), "=r"(r1), "=r"(r2), "=r"(r3) : "r"(addr));
}
__device__ __forceinline__ void mma_bf16(float* c, const uint32_t* a, const uint32_t* b) {
    asm volatile("mma.sync.aligned.m16n8k16.row.col.f32.bf16.bf16.f32 "
                 "{%0,%1,%2,%3}, {%4,%5,%6,%7}, {%8,%9}, {%0,%1,%2,%3};"
                 : "+f"(c[0]), "+f"(c[1]), "+f"(c[2]), "+f"(c[3])
                 : "r"(a[0]), "r"(a[1]), "r"(a[2]), "r"(a[3]), "r"(b[0]), "r"(b[1]));
}
#define CP16(dst, src) \
    asm volatile("cp.async.cg.shared.global [%0], [%1], 16;" :: "r"(dst), "l"(src))
#define CP_COMMIT() asm volatile("cp.async.commit_group;" ::: "memory")
#define CP_WAIT(n)  asm volatile("cp.async.wait_group %0;" :: "n"(n) : "memory")

__device__ __forceinline__ void split_bf16(float v, __nv_bfloat16& h, __nv_bfloat16& l) {
    h = __float2bfloat16(v);
    l = __float2bfloat16(v - __bfloat162float(h));
}
__device__ __forceinline__ void pack_hi_lo(float a, float b, uint32_t& hi, uint32_t& lo) {
    __nv_bfloat16 ha, la, hb, lb;
    split_bf16(a, ha, la); split_bf16(b, hb, lb);
    __nv_bfloat162 th = __halves2bfloat162(ha, hb);
    __nv_bfloat162 tl = __halves2bfloat162(la, lb);
    hi = *(uint32_t*)&th; lo = *(uint32_t*)&tl;
}
// 2^x via FMA pipe (no MUFU): magic rounding + degree-5 poly, rel err < 3e-6
__device__ __forceinline__ float exp2_fast(float x) {
    x = fmaxf(x, -120.f);
    float t = x + 12582912.f;
    float f = x - (t - 12582912.f);
    uint32_t ti = __float_as_uint(t);
    float s = __uint_as_float((ti << 23) + 0x3F800000u);
    float p = 1.33335581e-3f;
    p = fmaf(p, f, 9.61812911e-3f);
    p = fmaf(p, f, 5.55041087e-2f);
    p = fmaf(p, f, 2.40226507e-1f);
    p = fmaf(p, f, 6.93147181e-1f);
    p = fmaf(p, f, 1.0f);
    return p * s;
}

// ========================= bf16x3 GEMM body (64x64 tile, 3-stage) =============
// modes: 0 fp32 out; 1 (acc+bias)*scale -> bf16 hi/lo; 2 KV split; 3 gate epilogue
#define GKP 80
#define G_AHI 0
#define G_ALO 5120
#define G_BHI 10240
#define G_BLO 15360
#define G_STAGE 20480
#define SMEM_GM (3 * G_STAGE)                    // 61440 B

__device__ __forceinline__ void gemm_body(
    int bx, int by, char* smem,
    const __nv_bfloat16* __restrict__ Ahi, const __nv_bfloat16* __restrict__ Alo,
    const int* __restrict__ rowmap,
    const __nv_bfloat16* __restrict__ Bhi, const __nv_bfloat16* __restrict__ Blo,
    const float* __restrict__ bias, int M, int N, int mode, float scale,
    float* __restrict__ Cf, __nv_bfloat16* __restrict__ Chi, __nv_bfloat16* __restrict__ Clo,
    __nv_bfloat16* __restrict__ VThi, __nv_bfloat16* __restrict__ VTlo,
    const float* __restrict__ gw2, const float* __restrict__ gb2) {
    uint32_t sb = smem_u32(smem);
    int tid = threadIdx.x, wid = tid >> 5, lane = tid & 31;
    int rowBase = by * 64, colBase = bx * 64;
    int warp_m = (wid >> 2) * 32;
    int warp_n = (wid & 3) * 16;

    int ra = tid >> 2, ca = tid & 3;
    int gar = (rowBase + ra < M) ? (rowmap ? rowmap[rowBase + ra] : rowBase + ra) : 0;
    const __nv_bfloat16* sAh = Ahi + (size_t)gar * KD + ca * 8;
    const __nv_bfloat16* sAl = Alo + (size_t)gar * KD + ca * 8;
    const __nv_bfloat16* sBh = Bhi + (size_t)(colBase + ra) * KD + ca * 8;
    const __nv_bfloat16* sBl = Blo + (size_t)(colBase + ra) * KD + ca * 8;
    uint32_t dd = sb + (uint32_t)(ra * GKP + ca * 16);

    auto issue = [&](int kt, int st) {
        uint32_t so = (uint32_t)st * G_STAGE;
        int ko = kt * 32;
        CP16(dd + so + G_AHI, sAh + ko);
        CP16(dd + so + G_ALO, sAl + ko);
        CP16(dd + so + G_BHI, sBh + ko);
        CP16(dd + so + G_BLO, sBl + ko);
        CP_COMMIT();
    };

    uint32_t arel[2];
    #pragma unroll
    for (int mf = 0; mf < 2; mf++)
        arel[mf] = (uint32_t)((warp_m + mf * 16 + (lane & 15)) * GKP + (lane >> 4) * 16);
    int bg = lane >> 3, br = lane & 7;
    uint32_t brel = (uint32_t)((warp_n + (bg >> 1) * 8 + br) * GKP + (bg & 1) * 16);

    float acc[2][2][4] = {};

    issue(0, 0);
    issue(1, 1);
    #pragma unroll 1
    for (int kt = 0; kt < 8; kt++) {
        CP_WAIT(1);
        __syncthreads();
        if (kt < 6) issue(kt + 2, (kt + 2) % 3);
        uint32_t base = sb + (uint32_t)((kt % 3) * G_STAGE);
        #pragma unroll
        for (int kc = 0; kc < 2; kc++) {
            uint32_t koff = (uint32_t)kc * 32;
            uint32_t bh[2][2], bl[2][2];
            ldsm_x4(bh[0][0], bh[0][1], bh[1][0], bh[1][1], base + G_BHI + brel + koff);
            ldsm_x4(bl[0][0], bl[0][1], bl[1][0], bl[1][1], base + G_BLO + brel + koff);
            #pragma unroll
            for (int mf = 0; mf < 2; mf++) {
                uint32_t ah[4], al[4];
                ldsm_x4(ah[0], ah[1], ah[2], ah[3], base + G_AHI + arel[mf] + koff);
                ldsm_x4(al[0], al[1], al[2], al[3], base + G_ALO + arel[mf] + koff);
                #pragma unroll
                for (int nf = 0; nf < 2; nf++) {
                    mma_bf16(acc[mf][nf], ah, bh[nf]);
                    mma_bf16(acc[mf][nf], ah, bl[nf]);
                    mma_bf16(acc[mf][nf], al, bh[nf]);
                }
            }
        }
    }

    if (mode == 3) {
        // gate: relu(acc + b1) . w2, cross-warp reduce, sigmoid -> g_importance
        __syncthreads();
        float* red = (float*)smem;   // 64 rows x 4 n-warps
        float part[2][2];            // [mf][half]
        #pragma unroll
        for (int mf = 0; mf < 2; mf++)
            #pragma unroll
            for (int half = 0; half < 2; half++) part[mf][half] = 0.f;
        #pragma unroll
        for (int nf = 0; nf < 2; nf++) {
            #pragma unroll
            for (int j = 0; j < 2; j++) {
                int col = warp_n + nf * 8 + (lane & 3) * 2 + j;
                float b1v = __ldg(bias + col);
                float w2v = __ldg(gw2 + col);
                #pragma unroll
                for (int mf = 0; mf < 2; mf++)
                    #pragma unroll
                    for (int half = 0; half < 2; half++)
                        part[mf][half] += fmaxf(acc[mf][nf][half * 2 + j] + b1v, 0.f) * w2v;
            }
        }
        #pragma unroll
        for (int mf = 0; mf < 2; mf++)
            #pragma unroll
            for (int half = 0; half < 2; half++) {
                float p = part[mf][half];
                p += __shfl_xor_sync(0xffffffffu, p, 1);
                p += __shfl_xor_sync(0xffffffffu, p, 2);
                if ((lane & 3) == 0) {
                    int row = warp_m + mf * 16 + (lane >> 2) + half * 8;
                    red[row * 4 + (wid & 3)] = p;
                }
            }
        __syncthreads();
        if (tid < 64) {
            float s = red[tid * 4] + red[tid * 4 + 1] + red[tid * 4 + 2] + red[tid * 4 + 3];
            g_importance[rowBase + tid] = 1.f / (1.f + expf(-(s + gb2[0])));
        }
        return;
    }

    #pragma unroll
    for (int mf = 0; mf < 2; mf++) {
        #pragma unroll
        for (int nf = 0; nf < 2; nf++) {
            int n = colBase + warp_n + nf * 8 + (lane & 3) * 2;
            float b0 = __ldg(bias + n), b1 = __ldg(bias + n + 1);
            #pragma unroll
            for (int half = 0; half < 2; half++) {
                int m = rowBase + warp_m + mf * 16 + (lane >> 2) + half * 8;
                if (m >= M) continue;
                float o0 = acc[mf][nf][half * 2 + 0] + b0;
                float o1 = acc[mf][nf][half * 2 + 1] + b1;
                if (mode == 0) {
                    *(float2*)(Cf + (size_t)m * N + n) = make_float2(o0, o1);
                } else if (mode == 1) {
                    o0 *= scale; o1 *= scale;
                    __nv_bfloat16 h0, l0, h1, l1;
                    split_bf16(o0, h0, l0); split_bf16(o1, h1, l1);
                    *(__nv_bfloat162*)(Chi + (size_t)m * N + n) = __halves2bfloat162(h0, h1);
                    *(__nv_bfloat162*)(Clo + (size_t)m * N + n) = __halves2bfloat162(l0, l1);
                } else {
                    __nv_bfloat16 h0, l0, h1, l1;
                    split_bf16(o0, h0, l0); split_bf16(o1, h1, l1);
                    if (n < 256) {
                        *(__nv_bfloat162*)(Chi + (size_t)m * 256 + n) = __halves2bfloat162(h0, h1);
                        *(__nv_bfloat162*)(Clo + (size_t)m * 256 + n) = __halves2bfloat162(l0, l1);
                    } else {
                        int bb = m / KEEP, j = m - bb * KEEP;
                        int hh = (n - 256) >> 5, dd2 = (n - 256) & 31;
                        size_t i0 = ((size_t)(bb * H_ + hh) * HD_ + dd2) * KPAD + j;
                        size_t i1 = ((size_t)(bb * H_ + hh) * HD_ + dd2 + 1) * KPAD + j;
                        VThi[i0] = h0; VTlo[i0] = l0;
                        VThi[i1] = h1; VTlo[i1] = l1;
                    }
                }
            }
        }
    }
}

// ========================= launch 1: all conversions ==========================
#define CN1 (ROWS * D_ / 4)
#define CN2 (3 * D_ * D_ / 4)
#define CN3 (D_ * D_ / 4)
#define CN4 (64 * D_ / 4)
#define CONV_TOTAL (CN1 + CN2 + CN3 + CN4)

__global__ void convert_all(const float4* __restrict__ x,
                            const float4* __restrict__ w_in,
                            const float4* __restrict__ w_out,
                            const float4* __restrict__ gw1) {
    int i = blockIdx.x * blockDim.x + threadIdx.x;
    const float4* src;
    __nv_bfloat162 *hi, *lo;
    int off;
    if (i < CN1) {
        src = x; hi = (__nv_bfloat162*)g_xhi; lo = (__nv_bfloat162*)g_xlo; off = i;
    } else if (i < CN1 + CN2) {
        src = w_in; hi = (__nv_bfloat162*)g_winhi; lo = (__nv_bfloat162*)g_winlo; off = i - CN1;
    } else if (i < CN1 + CN2 + CN3) {
        src = w_out; hi = (__nv_bfloat162*)g_wouthi; lo = (__nv_bfloat162*)g_woutlo;
        off = i - CN1 - CN2;
    } else if (i < CONV_TOTAL) {
        src = gw1; hi = (__nv_bfloat162*)g_gw1hi; lo = (__nv_bfloat162*)g_gw1lo;
        off = i - CN1 - CN2 - CN3;
    } else return;
    float4 v = src[off];
    __nv_bfloat16 hx, hy, hz, hw, lx, ly, lz, lw;
    split_bf16(v.x, hx, lx); split_bf16(v.y, hy, ly);
    split_bf16(v.z, hz, lz); split_bf16(v.w, hw, lw);
    hi[2*off]   = __halves2bfloat162(hx, hy);
    hi[2*off+1] = __halves2bfloat162(hz, hw);
    lo[2*off]   = __halves2bfloat162(lx, ly);
    lo[2*off+1] = __halves2bfloat162(lz, lw);
}

// ========================= launch 2: gate MMA || Q GEMM =======================
#define GATE_BLOCKS (ROWS / 64)       // 128
#define QG_BLOCKS (4 * (ROWS / 64))   // 512

__global__ __launch_bounds__(256) void k_gate_qgemm(
    const float* __restrict__ gb1, const float* __restrict__ gw2,
    const float* __restrict__ gb2,
    const float* __restrict__ b_in, float qscale) {
    extern __shared__ char smem[];
    if (blockIdx.x < GATE_BLOCKS) {
        gemm_body(0, blockIdx.x, smem,
                  g_xhi, g_xlo, nullptr, g_gw1hi, g_gw1lo,
                  gb1, ROWS, 64, 3, 1.f,
                  nullptr, nullptr, nullptr, nullptr, nullptr, gw2, gb2);
        return;
    }
    int g = blockIdx.x - GATE_BLOCKS;
    gemm_body(g & 3, g >> 2, smem,
              g_xhi, g_xlo, nullptr, g_winhi, g_winlo,
              b_in, ROWS, D_, 1, qscale,
              nullptr, g_qhi, g_qlo, nullptr, nullptr, nullptr, nullptr);
}

// ========================= launch 3: radix top-k ==============================
__global__ __launch_bounds__(256) void k_topk() {
    __shared__ uint32_t bits[S_];
    __shared__ int hist[256];
    __shared__ int sc[4];
    __shared__ int eqlist[256];
    int b = blockIdx.x, t = threadIdx.x;
    for (int i = t; i < S_; i += 256)
        bits[i] = __float_as_uint(g_importance[b * S_ + i]);
    __syncthreads();

    uint32_t prefix = 0, prefmask = 0;
    int k_rem = KEEP;
    #pragma unroll
    for (int lev = 0; lev < 4; lev++) {
        int shift = 24 - lev * 8;
        hist[t] = 0;
        __syncthreads();
        for (int i = t; i < S_; i += 256) {
            uint32_t v = bits[i];
            if ((v & prefmask) == prefix) atomicAdd(&hist[(v >> shift) & 255], 1);
        }
        __syncthreads();
        if (t == 0) {
            int acc = 0, bin = 255;
            for (; bin > 0; bin--) {
                if (acc + hist[bin] >= k_rem) break;
                acc += hist[bin];
            }
            sc[0] = bin; sc[1] = acc;
        }
        __syncthreads();
        prefix |= ((uint32_t)sc[0]) << shift;
        prefmask |= (0xFFu << shift);
        k_rem -= sc[1];
        __syncthreads();
    }
    if (t == 0) { sc[2] = 0; sc[3] = 0; }
    __syncthreads();
    for (int i = t; i < S_; i += 256) {
        uint32_t v = bits[i];
        if (v > prefix) {
            int s = atomicAdd(&sc[2], 1);
            g_rowmap[b * KEEP + s] = b * S_ + i;
        } else if (v == prefix) {
            int s = atomicAdd(&sc[3], 1);
            if (s < 256) eqlist[s] = i;
        }
    }
    __syncthreads();
    int ne = min(sc[3], 256);
    if (t < ne) {
        int idx = eqlist[t], rank = 0;
        for (int j = 0; j < ne; j++) rank += (eqlist[j] < idx);
        if (rank < k_rem) g_rowmap[b * KEEP + sc[2] + rank] = b * S_ + idx;
    }
}

// ========================= launch 4: KV GEMM ==================================
__global__ __launch_bounds__(256) void k_kvgemm(const float* __restrict__ b_in) {
    extern __shared__ char smem[];
    gemm_body(blockIdx.x, blockIdx.y, smem,
              g_xhi, g_xlo, g_rowmap,
              g_winhi + D_ * D_, g_winlo + D_ * D_,
              b_in + D_, KV_ROWS, 2 * D_, 2, 1.f,
              nullptr, g_khi, g_klo, g_vthi, g_vtlo, nullptr, nullptr);
}

// ========================= launch 6: out-proj GEMM ============================
__global__ __launch_bounds__(256) void k_outgemm(
    const float* __restrict__ b_out, float* __restrict__ out) {
    extern __shared__ char smem[];
    gemm_body(blockIdx.x, blockIdx.y, smem,
              g_athi, g_atlo, nullptr, g_wouthi, g_woutlo,
              b_out, ROWS, D_, 0, 1.f,
              out, nullptr, nullptr, nullptr, nullptr, nullptr, nullptr);
}

// ========================= launch 5: MMA attention (key-chunked) ==============
#define PVS2 240
#define C_KHI 0
#define C_KLO 8960
#define C_VHI 17920
#define C_VLO (C_VHI + HD_ * PVS2)
#define SMEM_AT2 (C_VLO + HD_ * PVS2)      // 33280

__global__ __launch_bounds__(128, 4) void attn_mma() {
    extern __shared__ char smem[];
    uint32_t sb = smem_u32(smem);
    int tid = threadIdx.x, wid = tid >> 5, lane = tid & 31;
    int b = blockIdx.x >> 3, h = blockIdx.x & 7;
    int qbase = blockIdx.y * 64;
    int warp_m = wid * 16;
    int bg = lane >> 3, br = lane & 7;

    int qrow = qbase + warp_m + (lane >> 2);
    size_t q0 = (size_t)(b * S_ + qrow) * D_ + h * HD_ + (lane & 3) * 2;
    size_t q1 = q0 + 8 * (size_t)D_;
    uint32_t aqh[2][4], aql[2][4];
    #pragma unroll
    for (int ks = 0; ks < 2; ks++) {
        aqh[ks][0] = *(const uint32_t*)(g_qhi + q0 + ks * 16);
        aqh[ks][1] = *(const uint32_t*)(g_qhi + q1 + ks * 16);
        aqh[ks][2] = *(const uint32_t*)(g_qhi + q0 + 8 + ks * 16);
        aqh[ks][3] = *(const uint32_t*)(g_qhi + q1 + 8 + ks * 16);
        aql[ks][0] = *(const uint32_t*)(g_qlo + q0 + ks * 16);
        aql[ks][1] = *(const uint32_t*)(g_qlo + q1 + ks * 16);
        aql[ks][2] = *(const uint32_t*)(g_qlo + q0 + 8 + ks * 16);
        aql[ks][3] = *(const uint32_t*)(g_qlo + q1 + 8 + ks * 16);
    }

    uint32_t pbr0 = (uint32_t)(((bg >> 1) * 8 + br) * PVS2 + (bg & 1) * 16);
    uint32_t pbr1 = pbr0 + 16 * PVS2;

    float m0, m1, sum0 = 0.f, sum1 = 0.f;
    float oacc[4][4] = {};

    #pragma unroll
    for (int ch = 0; ch < 2; ch++) {
        int kb = ch * 112;
        if (ch) __syncthreads();
        for (int i = tid; i < 112 * 4; i += 128) {
            int j = i >> 2, c = i & 3;
            int gk = kb + j;
            uint4 vh = make_uint4(0, 0, 0, 0), vl = vh;
            if (gk < KEEP) {
                size_t off = (size_t)(b * KEEP + gk) * D_ + h * HD_ + c * 8;
                vh = *(const uint4*)(g_khi + off);
                vl = *(const uint4*)(g_klo + off);
            }
            *(uint4*)(smem + C_KHI + j * 80 + c * 16) = vh;
            *(uint4*)(smem + C_KLO + j * 80 + c * 16) = vl;
        }
        {
            int d = tid >> 2;
            size_t rowoff = ((size_t)(b * H_ + h) * HD_ + d) * KPAD + kb;
            for (int c = tid & 3; c < 14; c += 4) {
                int gkey = kb + c * 8;
                uint4 vh, vl;
                if (gkey + 8 <= KEEP) {
                    vh = *(const uint4*)(g_vthi + rowoff + c * 8);
                    vl = *(const uint4*)(g_vtlo + rowoff + c * 8);
                } else if (gkey < KEEP) {
                    uint2 th = *(const uint2*)(g_vthi + rowoff + c * 8);
                    uint2 tl = *(const uint2*)(g_vtlo + rowoff + c * 8);
                    vh = make_uint4(th.x, th.y, 0, 0);
                    vl = make_uint4(tl.x, tl.y, 0, 0);
                } else {
                    vh = make_uint4(0, 0, 0, 0); vl = vh;
                }
                *(uint4*)(smem + C_VHI + d * PVS2 + c * 16) = vh;
                *(uint4*)(smem + C_VLO + d * PVS2 + c * 16) = vl;
            }
        }
        __syncthreads();

        float sacc[14][4];
        #pragma unroll
        for (int t = 0; t < 14; t++)
            #pragma unroll
            for (int j = 0; j < 4; j++) sacc[t][j] = 0.f;

        #pragma unroll
        for (int nc = 0; nc < 7; nc++) {
            uint32_t brel = (uint32_t)((nc * 16 + (bg >> 1) * 8 + br) * 80 + (bg & 1) * 16);
            #pragma unroll
            for (int ks = 0; ks < 2; ks++) {
                uint32_t bh[2][2], bl[2][2];
                ldsm_x4(bh[0][0], bh[0][1], bh[1][0], bh[1][1], sb + C_KHI + brel + ks * 32);
                ldsm_x4(bl[0][0], bl[0][1], bl[1][0], bl[1][1], sb + C_KLO + brel + ks * 32);
                #pragma unroll
                for (int nf = 0; nf < 2; nf++) {
                    mma_bf16(sacc[nc * 2 + nf], aqh[ks], bh[nf]);
                    mma_bf16(sacc[nc * 2 + nf], aql[ks], bh[nf]);
                    mma_bf16(sacc[nc * 2 + nf], aqh[ks], bl[nf]);
                }
            }
        }

        if (ch == 1) {
            if ((lane & 3) >= 2) {
                sacc[11][0] = -1e30f; sacc[11][1] = -1e30f;
                sacc[11][2] = -1e30f; sacc[11][3] = -1e30f;
            }
            #pragma unroll
            for (int t = 12; t < 14; t++) {
                sacc[t][0] = -1e30f; sacc[t][1] = -1e30f;
                sacc[t][2] = -1e30f; sacc[t][3] = -1e30f;
            }
        }

        float cx0 = -1e30f, cx1 = -1e30f;
        #pragma unroll
        for (int t = 0; t < 14; t++) {
            cx0 = fmaxf(cx0, fmaxf(sacc[t][0], sacc[t][1]));
            cx1 = fmaxf(cx1, fmaxf(sacc[t][2], sacc[t][3]));
        }
        cx0 = fmaxf(cx0, __shfl_xor_sync(0xffffffffu, cx0, 1));
        cx0 = fmaxf(cx0, __shfl_xor_sync(0xffffffffu, cx0, 2));
        cx1 = fmaxf(cx1, __shfl_xor_sync(0xffffffffu, cx1, 1));
        cx1 = fmaxf(cx1, __shfl_xor_sync(0xffffffffu, cx1, 2));
        if (ch == 0) {
            m0 = cx0; m1 = cx1;
        } else {
            float nm0 = fmaxf(m0, cx0), nm1 = fmaxf(m1, cx1);
            float c0 = exp2_fast(m0 - nm0), c1 = exp2_fast(m1 - nm1);
            sum0 *= c0; sum1 *= c1;
            #pragma unroll
            for (int nf = 0; nf < 4; nf++) {
                oacc[nf][0] *= c0; oacc[nf][1] *= c0;
                oacc[nf][2] *= c1; oacc[nf][3] *= c1;
            }
            m0 = nm0; m1 = nm1;
        }

        #pragma unroll
        for (int t = 0; t < 14; t++) {
            sacc[t][0] = exp2_fast(sacc[t][0] - m0); sum0 += sacc[t][0];
            sacc[t][1] = exp2_fast(sacc[t][1] - m0); sum0 += sacc[t][1];
            sacc[t][2] = exp2_fast(sacc[t][2] - m1); sum1 += sacc[t][2];
            sacc[t][3] = exp2_fast(sacc[t][3] - m1); sum1 += sacc[t][3];
        }

        #pragma unroll
        for (int ks = 0; ks < 7; ks++) {
            uint32_t ph[4], pl[4];
            pack_hi_lo(sacc[2*ks][0],   sacc[2*ks][1],   ph[0], pl[0]);
            pack_hi_lo(sacc[2*ks][2],   sacc[2*ks][3],   ph[1], pl[1]);
            pack_hi_lo(sacc[2*ks+1][0], sacc[2*ks+1][1], ph[2], pl[2]);
            pack_hi_lo(sacc[2*ks+1][2], sacc[2*ks+1][3], ph[3], pl[3]);
            uint32_t koff = (uint32_t)ks * 32;
            uint32_t vh[4][2], vl[4][2];
            ldsm_x4(vh[0][0], vh[0][1], vh[1][0], vh[1][1], sb + C_VHI + pbr0 + koff);
            ldsm_x4(vh[2][0], vh[2][1], vh[3][0], vh[3][1], sb + C_VHI + pbr1 + koff);
            ldsm_x4(vl[0][0], vl[0][1], vl[1][0], vl[1][1], sb + C_VLO + pbr0 + koff);
            ldsm_x4(vl[2][0], vl[2][1], vl[3][0], vl[3][1], sb + C_VLO + pbr1 + koff);
            #pragma unroll
            for (int nf = 0; nf < 4; nf++) {
                mma_bf16(oacc[nf], ph, vh[nf]);
                mma_bf16(oacc[nf], pl, vh[nf]);
                mma_bf16(oacc[nf], ph, vl[nf]);
            }
        }
    }

    sum0 += __shfl_xor_sync(0xffffffffu, sum0, 1);
    sum0 += __shfl_xor_sync(0xffffffffu, sum0, 2);
    sum1 += __shfl_xor_sync(0xffffffffu, sum1, 1);
    sum1 += __shfl_xor_sync(0xffffffffu, sum1, 2);
    float inv0 = 1.f / sum0, inv1 = 1.f / sum1;

    #pragma unroll
    for (int nf = 0; nf < 4; nf++) {
        int col = h * HD_ + nf * 8 + (lane & 3) * 2;
        #pragma unroll
        for (int half = 0; half < 2; half++) {
            int row = warp_m + (lane >> 2) + half * 8;
            float il = half ? inv1 : inv0;
            float o0 = oacc[nf][half * 2 + 0] * il;
            float o1 = oacc[nf][half * 2 + 1] * il;
            __nv_bfloat16 h0, l0, h1, l1;
            split_bf16(o0, h0, l0); split_bf16(o1, h1, l1);
            size_t m = (size_t)(b * S_ + qbase + row) * D_ + col;
            *(__nv_bfloat162*)(g_athi + m) = __halves2bfloat162(h0, h1);
            *(__nv_bfloat162*)(g_atlo + m) = __halves2bfloat162(l0, l1);
        }
    }
}

// ------------------------- host launch ---------------------------------------
extern "C" void kernel_launch(void* const* d_in, const int* in_sizes, int n_in,
                              void* d_out, int out_size) {
    const float* x       = (const float*)d_in[0];
    const float* w_in    = (const float*)d_in[1];
    const float* b_in    = (const float*)d_in[2];
    const float* w_out   = (const float*)d_in[3];
    const float* b_out   = (const float*)d_in[4];
    const float* gate_w1 = (const float*)d_in[5];
    const float* gate_b1 = (const float*)d_in[6];
    const float* gate_w2 = (const float*)d_in[7];
    const float* gate_b2 = (const float*)d_in[8];
    float* out = (float*)d_out;

    cudaFuncSetAttribute(k_gate_qgemm, cudaFuncAttributeMaxDynamicSharedMemorySize, SMEM_GM);
    cudaFuncSetAttribute(k_kvgemm, cudaFuncAttributeMaxDynamicSharedMemorySize, SMEM_GM);
    cudaFuncSetAttribute(k_outgemm, cudaFuncAttributeMaxDynamicSharedMemorySize, SMEM_GM);
    cudaFuncSetAttribute(attn_mma, cudaFuncAttributeMaxDynamicSharedMemorySize, SMEM_AT2);

    // scale = log2(e) / sqrt(32): scores come out of QK^T in log2 domain
    const float qscale = 1.4426950408889634f * 0.17677669529663687f;

    // 1. fp32 -> bf16 hi/lo conversions (x, w_in, w_out, gate_w1)
    convert_all<<<(CONV_TOTAL + 255) / 256, 256>>>(
        (const float4*)x, (const float4*)w_in, (const float4*)w_out,
        (const float4*)gate_w1);

    // 2. gate GEMM (bf16x3 MMA, fused relu/dot/sigmoid) || Q projection GEMM
    k_gate_qgemm<<<GATE_BLOCKS + QG_BLOCKS, 256, SMEM_GM>>>(
        gate_b1, gate_w2, gate_b2, b_in, qscale);

    // 3. radix top-k -> rowmap
    k_topk<<<B_, 256>>>();

    // 4. K,V at kept rows -> K rows + V^T, bf16 hi/lo
    k_kvgemm<<<dim3((2 * D_) / 64, (KV_ROWS + 63) / 64), 256, SMEM_GM>>>(b_in);

    // 5. attention: key-chunked online softmax, 4 CTAs/SM
    attn_mma<<<dim3(B_ * H_, S_ / 64), 128, SMEM_AT2>>>();

    // 6. out projection (fp32 out)
    k_outgemm<<<dim3(D_ / 64, ROWS / 64), 256, SMEM_GM>>>(b_out, out);
}

// round 15
// speedup vs baseline: 1.1301x; 1.0024x over previous
#include <cuda_runtime.h>
#include <cuda_bf16.h>
#include <math_constants.h>
#include <cstdint>

#define B_   4
#define S_   2048
#define D_   256
#define H_   8
#define HD_  32
#define KEEP 204            // int(2048 * 0.1)
#define KPAD 208            // padded keys in global V^T layout
#define ROWS (B_ * S_)      // 8192
#define KV_ROWS (B_ * KEEP) // 816
#define KD   256

// ------------------------- scratch (static device globals) -------------------
__device__ float g_importance[ROWS];
__device__ int   g_rowmap[KV_ROWS];
__device__ __nv_bfloat16 g_xhi[ROWS * D_],   g_xlo[ROWS * D_];
__device__ __nv_bfloat16 g_winhi[3 * D_ * D_], g_winlo[3 * D_ * D_];
__device__ __nv_bfloat16 g_wouthi[D_ * D_],  g_woutlo[D_ * D_];
__device__ __nv_bfloat16 g_gw1hi[64 * D_],   g_gw1lo[64 * D_];
__device__ __nv_bfloat16 g_qhi[ROWS * D_],   g_qlo[ROWS * D_];      // Q * log2e/sqrt(hd)
__device__ __nv_bfloat16 g_khi[KV_ROWS * D_], g_klo[KV_ROWS * D_];
__device__ __nv_bfloat16 g_vthi[B_ * H_ * HD_ * KPAD], g_vtlo[B_ * H_ * HD_ * KPAD];
__device__ __nv_bfloat16 g_athi[ROWS * D_],  g_atlo[ROWS * D_];

// ========================= helpers ============================================
__device__ __forceinline__ uint32_t smem_u32(const void* p) {
    uint32_t a;
    asm("{ .reg .u64 t; cvta.to.shared.u64 t, %1; cvt.u32.u64 %0, t; }" : "=r"(a) : "l"(p));
    return a;
}
__device__ __forceinline__ void ldsm_x4(uint32_t& r0, uint32_t& r1, uint32_t& r2,
                                        uint32_t& r3, uint32_t addr) {
    asm volatile("ldmatrix.sync.aligned.m8n8.x4.shared.b16 {%0,%1,%2,%3}, [%4];"
                 : "=r"(r0), "=r"(r1), "=r"(r2), "=r"(r3) : "r"(addr));
}
__device__ __forceinline__ void mma_bf16(float* c, const uint32_t* a, const uint32_t* b) {
    asm volatile("mma.sync.aligned.m16n8k16.row.col.f32.bf16.bf16.f32 "
                 "{%0,%1,%2,%3}, {%4,%5,%6,%7}, {%8,%9}, {%0,%1,%2,%3};"
                 : "+f"(c[0]), "+f"(c[1]), "+f"(c[2]), "+f"(c[3])
                 : "r"(a[0]), "r"(a[1]), "r"(a[2]), "r"(a[3]), "r"(b[0]), "r"(b[1]));
}
#define CP16(dst, src) \
    asm volatile("cp.async.cg.shared.global [%0], [%1], 16;" :: "r"(dst), "l"(src))
#define CP_COMMIT() asm volatile("cp.async.commit_group;" ::: "memory")
#define CP_WAIT(n)  asm volatile("cp.async.wait_group %0;" :: "n"(n) : "memory")

__device__ __forceinline__ void split_bf16(float v, __nv_bfloat16& h, __nv_bfloat16& l) {
    h = __float2bfloat16(v);
    l = __float2bfloat16(v - __bfloat162float(h));
}
__device__ __forceinline__ void pack_hi_lo(float a, float b, uint32_t& hi, uint32_t& lo) {
    __nv_bfloat16 ha, la, hb, lb;
    split_bf16(a, ha, la); split_bf16(b, hb, lb);
    __nv_bfloat162 th = __halves2bfloat162(ha, hb);
    __nv_bfloat162 tl = __halves2bfloat162(la, lb);
    hi = *(uint32_t*)&th; lo = *(uint32_t*)&tl;
}
// 2^x via FMA pipe (no MUFU): magic rounding + degree-5 poly, rel err < 3e-6
__device__ __forceinline__ float exp2_fast(float x) {
    x = fmaxf(x, -120.f);
    float t = x + 12582912.f;
    float f = x - (t - 12582912.f);
    uint32_t ti = __float_as_uint(t);
    float s = __uint_as_float((ti << 23) + 0x3F800000u);
    float p = 1.33335581e-3f;
    p = fmaf(p, f, 9.61812911e-3f);
    p = fmaf(p, f, 5.55041087e-2f);
    p = fmaf(p, f, 2.40226507e-1f);
    p = fmaf(p, f, 6.93147181e-1f);
    p = fmaf(p, f, 1.0f);
    return p * s;
}

// ========================= bf16x3 GEMM body (64x64 tile, 3-stage) =============
// modes: 0 fp32 out; 1 (acc+bias)*scale -> bf16 hi/lo; 2 KV split; 3 gate epilogue
#define GKP 80
#define G_AHI 0
#define G_ALO 5120
#define G_BHI 10240
#define G_BLO 15360
#define G_STAGE 20480
#define SMEM_GM (3 * G_STAGE)                    // 61440 B
#define SMEM_KV (8 * G_STAGE)                    // 163840 B (full-K resident)

__device__ __forceinline__ void gemm_body(
    int bx, int by, char* smem,
    const __nv_bfloat16* __restrict__ Ahi, const __nv_bfloat16* __restrict__ Alo,
    const int* __restrict__ rowmap,
    const __nv_bfloat16* __restrict__ Bhi, const __nv_bfloat16* __restrict__ Blo,
    const float* __restrict__ bias, int M, int N, int mode, float scale,
    float* __restrict__ Cf, __nv_bfloat16* __restrict__ Chi, __nv_bfloat16* __restrict__ Clo,
    __nv_bfloat16* __restrict__ VThi, __nv_bfloat16* __restrict__ VTlo,
    const float* __restrict__ gw2, const float* __restrict__ gb2) {
    uint32_t sb = smem_u32(smem);
    int tid = threadIdx.x, wid = tid >> 5, lane = tid & 31;
    int rowBase = by * 64, colBase = bx * 64;
    int warp_m = (wid >> 2) * 32;
    int warp_n = (wid & 3) * 16;

    int ra = tid >> 2, ca = tid & 3;
    int gar = (rowBase + ra < M) ? (rowmap ? rowmap[rowBase + ra] : rowBase + ra) : 0;
    const __nv_bfloat16* sAh = Ahi + (size_t)gar * KD + ca * 8;
    const __nv_bfloat16* sAl = Alo + (size_t)gar * KD + ca * 8;
    const __nv_bfloat16* sBh = Bhi + (size_t)(colBase + ra) * KD + ca * 8;
    const __nv_bfloat16* sBl = Blo + (size_t)(colBase + ra) * KD + ca * 8;
    uint32_t dd = sb + (uint32_t)(ra * GKP + ca * 16);

    auto issue = [&](int kt, int st) {
        uint32_t so = (uint32_t)st * G_STAGE;
        int ko = kt * 32;
        CP16(dd + so + G_AHI, sAh + ko);
        CP16(dd + so + G_ALO, sAl + ko);
        CP16(dd + so + G_BHI, sBh + ko);
        CP16(dd + so + G_BLO, sBl + ko);
        CP_COMMIT();
    };

    uint32_t arel[2];
    #pragma unroll
    for (int mf = 0; mf < 2; mf++)
        arel[mf] = (uint32_t)((warp_m + mf * 16 + (lane & 15)) * GKP + (lane >> 4) * 16);
    int bg = lane >> 3, br = lane & 7;
    uint32_t brel = (uint32_t)((warp_n + (bg >> 1) * 8 + br) * GKP + (bg & 1) * 16);

    float acc[2][2][4] = {};

    issue(0, 0);
    issue(1, 1);
    #pragma unroll 1
    for (int kt = 0; kt < 8; kt++) {
        CP_WAIT(1);
        __syncthreads();
        if (kt < 6) issue(kt + 2, (kt + 2) % 3);
        uint32_t base = sb + (uint32_t)((kt % 3) * G_STAGE);
        #pragma unroll
        for (int kc = 0; kc < 2; kc++) {
            uint32_t koff = (uint32_t)kc * 32;
            uint32_t bh[2][2], bl[2][2];
            ldsm_x4(bh[0][0], bh[0][1], bh[1][0], bh[1][1], base + G_BHI + brel + koff);
            ldsm_x4(bl[0][0], bl[0][1], bl[1][0], bl[1][1], base + G_BLO + brel + koff);
            #pragma unroll
            for (int mf = 0; mf < 2; mf++) {
                uint32_t ah[4], al[4];
                ldsm_x4(ah[0], ah[1], ah[2], ah[3], base + G_AHI + arel[mf] + koff);
                ldsm_x4(al[0], al[1], al[2], al[3], base + G_ALO + arel[mf] + koff);
                #pragma unroll
                for (int nf = 0; nf < 2; nf++) {
                    mma_bf16(acc[mf][nf], ah, bh[nf]);
                    mma_bf16(acc[mf][nf], ah, bl[nf]);
                    mma_bf16(acc[mf][nf], al, bh[nf]);
                }
            }
        }
    }

    if (mode == 3) {
        __syncthreads();
        float* red = (float*)smem;
        float part[2][2];
        #pragma unroll
        for (int mf = 0; mf < 2; mf++)
            #pragma unroll
            for (int half = 0; half < 2; half++) part[mf][half] = 0.f;
        #pragma unroll
        for (int nf = 0; nf < 2; nf++) {
            #pragma unroll
            for (int j = 0; j < 2; j++) {
                int col = warp_n + nf * 8 + (lane & 3) * 2 + j;
                float b1v = __ldg(bias + col);
                float w2v = __ldg(gw2 + col);
                #pragma unroll
                for (int mf = 0; mf < 2; mf++)
                    #pragma unroll
                    for (int half = 0; half < 2; half++)
                        part[mf][half] += fmaxf(acc[mf][nf][half * 2 + j] + b1v, 0.f) * w2v;
            }
        }
        #pragma unroll
        for (int mf = 0; mf < 2; mf++)
            #pragma unroll
            for (int half = 0; half < 2; half++) {
                float p = part[mf][half];
                p += __shfl_xor_sync(0xffffffffu, p, 1);
                p += __shfl_xor_sync(0xffffffffu, p, 2);
                if ((lane & 3) == 0) {
                    int row = warp_m + mf * 16 + (lane >> 2) + half * 8;
                    red[row * 4 + (wid & 3)] = p;
                }
            }
        __syncthreads();
        if (tid < 64) {
            float s = red[tid * 4] + red[tid * 4 + 1] + red[tid * 4 + 2] + red[tid * 4 + 3];
            g_importance[rowBase + tid] = 1.f / (1.f + expf(-(s + gb2[0])));
        }
        return;
    }

    #pragma unroll
    for (int mf = 0; mf < 2; mf++) {
        #pragma unroll
        for (int nf = 0; nf < 2; nf++) {
            int n = colBase + warp_n + nf * 8 + (lane & 3) * 2;
            float b0 = __ldg(bias + n), b1 = __ldg(bias + n + 1);
            #pragma unroll
            for (int half = 0; half < 2; half++) {
                int m = rowBase + warp_m + mf * 16 + (lane >> 2) + half * 8;
                if (m >= M) continue;
                float o0 = acc[mf][nf][half * 2 + 0] + b0;
                float o1 = acc[mf][nf][half * 2 + 1] + b1;
                if (mode == 0) {
                    *(float2*)(Cf + (size_t)m * N + n) = make_float2(o0, o1);
                } else if (mode == 1) {
                    o0 *= scale; o1 *= scale;
                    __nv_bfloat16 h0, l0, h1, l1;
                    split_bf16(o0, h0, l0); split_bf16(o1, h1, l1);
                    *(__nv_bfloat162*)(Chi + (size_t)m * N + n) = __halves2bfloat162(h0, h1);
                    *(__nv_bfloat162*)(Clo + (size_t)m * N + n) = __halves2bfloat162(l0, l1);
                } else {
                    __nv_bfloat16 h0, l0, h1, l1;
                    split_bf16(o0, h0, l0); split_bf16(o1, h1, l1);
                    if (n < 256) {
                        *(__nv_bfloat162*)(Chi + (size_t)m * 256 + n) = __halves2bfloat162(h0, h1);
                        *(__nv_bfloat162*)(Clo + (size_t)m * 256 + n) = __halves2bfloat162(l0, l1);
                    } else {
                        int bb = m / KEEP, j = m - bb * KEEP;
                        int hh = (n - 256) >> 5, dd2 = (n - 256) & 31;
                        size_t i0 = ((size_t)(bb * H_ + hh) * HD_ + dd2) * KPAD + j;
                        size_t i1 = ((size_t)(bb * H_ + hh) * HD_ + dd2 + 1) * KPAD + j;
                        VThi[i0] = h0; VTlo[i0] = l0;
                        VThi[i1] = h1; VTlo[i1] = l1;
                    }
                }
            }
        }
    }
}

// ========== KV GEMM body: full-K resident (8 stages), one wait, one sync =====
__device__ __forceinline__ void gemm_kv_body(
    int bx, int by, char* smem, const float* __restrict__ bias) {
    uint32_t sb = smem_u32(smem);
    int tid = threadIdx.x, wid = tid >> 5, lane = tid & 31;
    int rowBase = by * 64, colBase = bx * 64;
    int warp_m = (wid >> 2) * 32;
    int warp_n = (wid & 3) * 16;
    const __nv_bfloat16* Bhi = g_winhi + D_ * D_;
    const __nv_bfloat16* Blo = g_winlo + D_ * D_;

    int ra = tid >> 2, ca = tid & 3;
    int gar = (rowBase + ra < KV_ROWS) ? g_rowmap[rowBase + ra] : 0;
    const __nv_bfloat16* sAh = g_xhi + (size_t)gar * KD + ca * 8;
    const __nv_bfloat16* sAl = g_xlo + (size_t)gar * KD + ca * 8;
    const __nv_bfloat16* sBh = Bhi + (size_t)(colBase + ra) * KD + ca * 8;
    const __nv_bfloat16* sBl = Blo + (size_t)(colBase + ra) * KD + ca * 8;
    uint32_t dd = sb + (uint32_t)(ra * GKP + ca * 16);

    // issue ALL 8 k-tiles upfront; single wait + single barrier
    #pragma unroll
    for (int kt = 0; kt < 8; kt++) {
        uint32_t so = (uint32_t)kt * G_STAGE;
        int ko = kt * 32;
        CP16(dd + so + G_AHI, sAh + ko);
        CP16(dd + so + G_ALO, sAl + ko);
        CP16(dd + so + G_BHI, sBh + ko);
        CP16(dd + so + G_BLO, sBl + ko);
    }
    CP_COMMIT();
    CP_WAIT(0);
    __syncthreads();

    uint32_t arel[2];
    #pragma unroll
    for (int mf = 0; mf < 2; mf++)
        arel[mf] = (uint32_t)((warp_m + mf * 16 + (lane & 15)) * GKP + (lane >> 4) * 16);
    int bg = lane >> 3, br = lane & 7;
    uint32_t brel = (uint32_t)((warp_n + (bg >> 1) * 8 + br) * GKP + (bg & 1) * 16);

    float acc[2][2][4] = {};

    #pragma unroll
    for (int kt = 0; kt < 8; kt++) {
        uint32_t base = sb + (uint32_t)(kt * G_STAGE);
        #pragma unroll
        for (int kc = 0; kc < 2; kc++) {
            uint32_t koff = (uint32_t)kc * 32;
            uint32_t bh[2][2], bl[2][2];
            ldsm_x4(bh[0][0], bh[0][1], bh[1][0], bh[1][1], base + G_BHI + brel + koff);
            ldsm_x4(bl[0][0], bl[0][1], bl[1][0], bl[1][1], base + G_BLO + brel + koff);
            #pragma unroll
            for (int mf = 0; mf < 2; mf++) {
                uint32_t ah[4], al[4];
                ldsm_x4(ah[0], ah[1], ah[2], ah[3], base + G_AHI + arel[mf] + koff);
                ldsm_x4(al[0], al[1], al[2], al[3], base + G_ALO + arel[mf] + koff);
                #pragma unroll
                for (int nf = 0; nf < 2; nf++) {
                    mma_bf16(acc[mf][nf], ah, bh[nf]);
                    mma_bf16(acc[mf][nf], ah, bl[nf]);
                    mma_bf16(acc[mf][nf], al, bh[nf]);
                }
            }
        }
    }

    // mode-2 epilogue: K rows + V^T split
    #pragma unroll
    for (int mf = 0; mf < 2; mf++) {
        #pragma unroll
        for (int nf = 0; nf < 2; nf++) {
            int n = colBase + warp_n + nf * 8 + (lane & 3) * 2;
            float b0 = __ldg(bias + n), b1 = __ldg(bias + n + 1);
            #pragma unroll
            for (int half = 0; half < 2; half++) {
                int m = rowBase + warp_m + mf * 16 + (lane >> 2) + half * 8;
                if (m >= KV_ROWS) continue;
                float o0 = acc[mf][nf][half * 2 + 0] + b0;
                float o1 = acc[mf][nf][half * 2 + 1] + b1;
                __nv_bfloat16 h0, l0, h1, l1;
                split_bf16(o0, h0, l0); split_bf16(o1, h1, l1);
                if (n < 256) {
                    *(__nv_bfloat162*)(g_khi + (size_t)m * 256 + n) = __halves2bfloat162(h0, h1);
                    *(__nv_bfloat162*)(g_klo + (size_t)m * 256 + n) = __halves2bfloat162(l0, l1);
                } else {
                    int bb = m / KEEP, j = m - bb * KEEP;
                    int hh = (n - 256) >> 5, dd2 = (n - 256) & 31;
                    size_t i0 = ((size_t)(bb * H_ + hh) * HD_ + dd2) * KPAD + j;
                    size_t i1 = ((size_t)(bb * H_ + hh) * HD_ + dd2 + 1) * KPAD + j;
                    g_vthi[i0] = h0; g_vtlo[i0] = l0;
                    g_vthi[i1] = h1; g_vtlo[i1] = l1;
                }
            }
        }
    }
}

// ========================= launch 1: all conversions ==========================
#define CN1 (ROWS * D_ / 4)
#define CN2 (3 * D_ * D_ / 4)
#define CN3 (D_ * D_ / 4)
#define CN4 (64 * D_ / 4)
#define CONV_TOTAL (CN1 + CN2 + CN3 + CN4)

__global__ void convert_all(const float4* __restrict__ x,
                            const float4* __restrict__ w_in,
                            const float4* __restrict__ w_out,
                            const float4* __restrict__ gw1) {
    int i = blockIdx.x * blockDim.x + threadIdx.x;
    const float4* src;
    __nv_bfloat162 *hi, *lo;
    int off;
    if (i < CN1) {
        src = x; hi = (__nv_bfloat162*)g_xhi; lo = (__nv_bfloat162*)g_xlo; off = i;
    } else if (i < CN1 + CN2) {
        src = w_in; hi = (__nv_bfloat162*)g_winhi; lo = (__nv_bfloat162*)g_winlo; off = i - CN1;
    } else if (i < CN1 + CN2 + CN3) {
        src = w_out; hi = (__nv_bfloat162*)g_wouthi; lo = (__nv_bfloat162*)g_woutlo;
        off = i - CN1 - CN2;
    } else if (i < CONV_TOTAL) {
        src = gw1; hi = (__nv_bfloat162*)g_gw1hi; lo = (__nv_bfloat162*)g_gw1lo;
        off = i - CN1 - CN2 - CN3;
    } else return;
    float4 v = src[off];
    __nv_bfloat16 hx, hy, hz, hw, lx, ly, lz, lw;
    split_bf16(v.x, hx, lx); split_bf16(v.y, hy, ly);
    split_bf16(v.z, hz, lz); split_bf16(v.w, hw, lw);
    hi[2*off]   = __halves2bfloat162(hx, hy);
    hi[2*off+1] = __halves2bfloat162(hz, hw);
    lo[2*off]   = __halves2bfloat162(lx, ly);
    lo[2*off+1] = __halves2bfloat162(lz, lw);
}

// ========================= launch 2: gate MMA || Q GEMM =======================
#define GATE_BLOCKS (ROWS / 64)       // 128
#define QG_BLOCKS (4 * (ROWS / 64))   // 512

__global__ __launch_bounds__(256) void k_gate_qgemm(
    const float* __restrict__ gb1, const float* __restrict__ gw2,
    const float* __restrict__ gb2,
    const float* __restrict__ b_in, float qscale) {
    extern __shared__ char smem[];
    if (blockIdx.x < GATE_BLOCKS) {
        gemm_body(0, blockIdx.x, smem,
                  g_xhi, g_xlo, nullptr, g_gw1hi, g_gw1lo,
                  gb1, ROWS, 64, 3, 1.f,
                  nullptr, nullptr, nullptr, nullptr, nullptr, gw2, gb2);
        return;
    }
    int g = blockIdx.x - GATE_BLOCKS;
    gemm_body(g & 3, g >> 2, smem,
              g_xhi, g_xlo, nullptr, g_winhi, g_winlo,
              b_in, ROWS, D_, 1, qscale,
              nullptr, g_qhi, g_qlo, nullptr, nullptr, nullptr, nullptr);
}

// ========================= launch 3: radix top-k ==============================
__global__ __launch_bounds__(256) void k_topk() {
    __shared__ uint32_t bits[S_];
    __shared__ int hist[256];
    __shared__ int sc[4];
    __shared__ int eqlist[256];
    int b = blockIdx.x, t = threadIdx.x;
    for (int i = t; i < S_; i += 256)
        bits[i] = __float_as_uint(g_importance[b * S_ + i]);
    __syncthreads();

    uint32_t prefix = 0, prefmask = 0;
    int k_rem = KEEP;
    #pragma unroll
    for (int lev = 0; lev < 4; lev++) {
        int shift = 24 - lev * 8;
        hist[t] = 0;
        __syncthreads();
        for (int i = t; i < S_; i += 256) {
            uint32_t v = bits[i];
            if ((v & prefmask) == prefix) atomicAdd(&hist[(v >> shift) & 255], 1);
        }
        __syncthreads();
        if (t == 0) {
            int acc = 0, bin = 255;
            for (; bin > 0; bin--) {
                if (acc + hist[bin] >= k_rem) break;
                acc += hist[bin];
            }
            sc[0] = bin; sc[1] = acc;
        }
        __syncthreads();
        prefix |= ((uint32_t)sc[0]) << shift;
        prefmask |= (0xFFu << shift);
        k_rem -= sc[1];
        __syncthreads();
    }
    if (t == 0) { sc[2] = 0; sc[3] = 0; }
    __syncthreads();
    for (int i = t; i < S_; i += 256) {
        uint32_t v = bits[i];
        if (v > prefix) {
            int s = atomicAdd(&sc[2], 1);
            g_rowmap[b * KEEP + s] = b * S_ + i;
        } else if (v == prefix) {
            int s = atomicAdd(&sc[3], 1);
            if (s < 256) eqlist[s] = i;
        }
    }
    __syncthreads();
    int ne = min(sc[3], 256);
    if (t < ne) {
        int idx = eqlist[t], rank = 0;
        for (int j = 0; j < ne; j++) rank += (eqlist[j] < idx);
        if (rank < k_rem) g_rowmap[b * KEEP + sc[2] + rank] = b * S_ + idx;
    }
}

// ========================= launch 4: KV GEMM (full-K resident) ================
__global__ __launch_bounds__(256) void k_kvgemm(const float* __restrict__ b_in) {
    extern __shared__ char smem[];
    gemm_kv_body(blockIdx.x, blockIdx.y, smem, b_in + D_);
}

// ========================= launch 6: out-proj GEMM ============================
__global__ __launch_bounds__(256) void k_outgemm(
    const float* __restrict__ b_out, float* __restrict__ out) {
    extern __shared__ char smem[];
    gemm_body(blockIdx.x, blockIdx.y, smem,
              g_athi, g_atlo, nullptr, g_wouthi, g_woutlo,
              b_out, ROWS, D_, 0, 1.f,
              out, nullptr, nullptr, nullptr, nullptr, nullptr, nullptr);
}

// ========================= launch 5: MMA attention (key-chunked) ==============
#define PVS2 240
#define C_KHI 0
#define C_KLO 8960
#define C_VHI 17920
#define C_VLO (C_VHI + HD_ * PVS2)
#define SMEM_AT2 (C_VLO + HD_ * PVS2)      // 33280

__global__ __launch_bounds__(128, 4) void attn_mma() {
    extern __shared__ char smem[];
    uint32_t sb = smem_u32(smem);
    int tid = threadIdx.x, wid = tid >> 5, lane = tid & 31;
    int b = blockIdx.x >> 3, h = blockIdx.x & 7;
    int qbase = blockIdx.y * 64;
    int warp_m = wid * 16;
    int bg = lane >> 3, br = lane & 7;

    int qrow = qbase + warp_m + (lane >> 2);
    size_t q0 = (size_t)(b * S_ + qrow) * D_ + h * HD_ + (lane & 3) * 2;
    size_t q1 = q0 + 8 * (size_t)D_;
    uint32_t aqh[2][4], aql[2][4];
    #pragma unroll
    for (int ks = 0; ks < 2; ks++) {
        aqh[ks][0] = *(const uint32_t*)(g_qhi + q0 + ks * 16);
        aqh[ks][1] = *(const uint32_t*)(g_qhi + q1 + ks * 16);
        aqh[ks][2] = *(const uint32_t*)(g_qhi + q0 + 8 + ks * 16);
        aqh[ks][3] = *(const uint32_t*)(g_qhi + q1 + 8 + ks * 16);
        aql[ks][0] = *(const uint32_t*)(g_qlo + q0 + ks * 16);
        aql[ks][1] = *(const uint32_t*)(g_qlo + q1 + ks * 16);
        aql[ks][2] = *(const uint32_t*)(g_qlo + q0 + 8 + ks * 16);
        aql[ks][3] = *(const uint32_t*)(g_qlo + q1 + 8 + ks * 16);
    }

    uint32_t pbr0 = (uint32_t)(((bg >> 1) * 8 + br) * PVS2 + (bg & 1) * 16);
    uint32_t pbr1 = pbr0 + 16 * PVS2;

    float m0, m1, sum0 = 0.f, sum1 = 0.f;
    float oacc[4][4] = {};

    #pragma unroll
    for (int ch = 0; ch < 2; ch++) {
        int kb = ch * 112;
        if (ch) __syncthreads();
        for (int i = tid; i < 112 * 4; i += 128) {
            int j = i >> 2, c = i & 3;
            int gk = kb + j;
            uint4 vh = make_uint4(0, 0, 0, 0), vl = vh;
            if (gk < KEEP) {
                size_t off = (size_t)(b * KEEP + gk) * D_ + h * HD_ + c * 8;
                vh = *(const uint4*)(g_khi + off);
                vl = *(const uint4*)(g_klo + off);
            }
            *(uint4*)(smem + C_KHI + j * 80 + c * 16) = vh;
            *(uint4*)(smem + C_KLO + j * 80 + c * 16) = vl;
        }
        {
            int d = tid >> 2;
            size_t rowoff = ((size_t)(b * H_ + h) * HD_ + d) * KPAD + kb;
            for (int c = tid & 3; c < 14; c += 4) {
                int gkey = kb + c * 8;
                uint4 vh, vl;
                if (gkey + 8 <= KEEP) {
                    vh = *(const uint4*)(g_vthi + rowoff + c * 8);
                    vl = *(const uint4*)(g_vtlo + rowoff + c * 8);
                } else if (gkey < KEEP) {
                    uint2 th = *(const uint2*)(g_vthi + rowoff + c * 8);
                    uint2 tl = *(const uint2*)(g_vtlo + rowoff + c * 8);
                    vh = make_uint4(th.x, th.y, 0, 0);
                    vl = make_uint4(tl.x, tl.y, 0, 0);
                } else {
                    vh = make_uint4(0, 0, 0, 0); vl = vh;
                }
                *(uint4*)(smem + C_VHI + d * PVS2 + c * 16) = vh;
                *(uint4*)(smem + C_VLO + d * PVS2 + c * 16) = vl;
            }
        }
        __syncthreads();

        float sacc[14][4];
        #pragma unroll
        for (int t = 0; t < 14; t++)
            #pragma unroll
            for (int j = 0; j < 4; j++) sacc[t][j] = 0.f;

        #pragma unroll
        for (int nc = 0; nc < 7; nc++) {
            uint32_t brel = (uint32_t)((nc * 16 + (bg >> 1) * 8 + br) * 80 + (bg & 1) * 16);
            #pragma unroll
            for (int ks = 0; ks < 2; ks++) {
                uint32_t bh[2][2], bl[2][2];
                ldsm_x4(bh[0][0], bh[0][1], bh[1][0], bh[1][1], sb + C_KHI + brel + ks * 32);
                ldsm_x4(bl[0][0], bl[0][1], bl[1][0], bl[1][1], sb + C_KLO + brel + ks * 32);
                #pragma unroll
                for (int nf = 0; nf < 2; nf++) {
                    mma_bf16(sacc[nc * 2 + nf], aqh[ks], bh[nf]);
                    mma_bf16(sacc[nc * 2 + nf], aql[ks], bh[nf]);
                    mma_bf16(sacc[nc * 2 + nf], aqh[ks], bl[nf]);
                }
            }
        }

        if (ch == 1) {
            if ((lane & 3) >= 2) {
                sacc[11][0] = -1e30f; sacc[11][1] = -1e30f;
                sacc[11][2] = -1e30f; sacc[11][3] = -1e30f;
            }
            #pragma unroll
            for (int t = 12; t < 14; t++) {
                sacc[t][0] = -1e30f; sacc[t][1] = -1e30f;
                sacc[t][2] = -1e30f; sacc[t][3] = -1e30f;
            }
        }

        float cx0 = -1e30f, cx1 = -1e30f;
        #pragma unroll
        for (int t = 0; t < 14; t++) {
            cx0 = fmaxf(cx0, fmaxf(sacc[t][0], sacc[t][1]));
            cx1 = fmaxf(cx1, fmaxf(sacc[t][2], sacc[t][3]));
        }
        cx0 = fmaxf(cx0, __shfl_xor_sync(0xffffffffu, cx0, 1));
        cx0 = fmaxf(cx0, __shfl_xor_sync(0xffffffffu, cx0, 2));
        cx1 = fmaxf(cx1, __shfl_xor_sync(0xffffffffu, cx1, 1));
        cx1 = fmaxf(cx1, __shfl_xor_sync(0xffffffffu, cx1, 2));
        if (ch == 0) {
            m0 = cx0; m1 = cx1;
        } else {
            float nm0 = fmaxf(m0, cx0), nm1 = fmaxf(m1, cx1);
            float c0 = exp2_fast(m0 - nm0), c1 = exp2_fast(m1 - nm1);
            sum0 *= c0; sum1 *= c1;
            #pragma unroll
            for (int nf = 0; nf < 4; nf++) {
                oacc[nf][0] *= c0; oacc[nf][1] *= c0;
                oacc[nf][2] *= c1; oacc[nf][3] *= c1;
            }
            m0 = nm0; m1 = nm1;
        }

        #pragma unroll
        for (int t = 0; t < 14; t++) {
            sacc[t][0] = exp2_fast(sacc[t][0] - m0); sum0 += sacc[t][0];
            sacc[t][1] = exp2_fast(sacc[t][1] - m0); sum0 += sacc[t][1];
            sacc[t][2] = exp2_fast(sacc[t][2] - m1); sum1 += sacc[t][2];
            sacc[t][3] = exp2_fast(sacc[t][3] - m1); sum1 += sacc[t][3];
        }

        #pragma unroll
        for (int ks = 0; ks < 7; ks++) {
            uint32_t ph[4], pl[4];
            pack_hi_lo(sacc[2*ks][0],   sacc[2*ks][1],   ph[0], pl[0]);
            pack_hi_lo(sacc[2*ks][2],   sacc[2*ks][3],   ph[1], pl[1]);
            pack_hi_lo(sacc[2*ks+1][0], sacc[2*ks+1][1], ph[2], pl[2]);
            pack_hi_lo(sacc[2*ks+1][2], sacc[2*ks+1][3], ph[3], pl[3]);
            uint32_t koff = (uint32_t)ks * 32;
            uint32_t vh[4][2], vl[4][2];
            ldsm_x4(vh[0][0], vh[0][1], vh[1][0], vh[1][1], sb + C_VHI + pbr0 + koff);
            ldsm_x4(vh[2][0], vh[2][1], vh[3][0], vh[3][1], sb + C_VHI + pbr1 + koff);
            ldsm_x4(vl[0][0], vl[0][1], vl[1][0], vl[1][1], sb + C_VLO + pbr0 + koff);
            ldsm_x4(vl[2][0], vl[2][1], vl[3][0], vl[3][1], sb + C_VLO + pbr1 + koff);
            #pragma unroll
            for (int nf = 0; nf < 4; nf++) {
                mma_bf16(oacc[nf], ph, vh[nf]);
                mma_bf16(oacc[nf], pl, vh[nf]);
                mma_bf16(oacc[nf], ph, vl[nf]);
            }
        }
    }

    sum0 += __shfl_xor_sync(0xffffffffu, sum0, 1);
    sum0 += __shfl_xor_sync(0xffffffffu, sum0, 2);
    sum1 += __shfl_xor_sync(0xffffffffu, sum1, 1);
    sum1 += __shfl_xor_sync(0xffffffffu, sum1, 2);
    float inv0 = 1.f / sum0, inv1 = 1.f / sum1;

    #pragma unroll
    for (int nf = 0; nf < 4; nf++) {
        int col = h * HD_ + nf * 8 + (lane & 3) * 2;
        #pragma unroll
        for (int half = 0; half < 2; half++) {
            int row = warp_m + (lane >> 2) + half * 8;
            float il = half ? inv1 : inv0;
            float o0 = oacc[nf][half * 2 + 0] * il;
            float o1 = oacc[nf][half * 2 + 1] * il;
            __nv_bfloat16 h0, l0, h1, l1;
            split_bf16(o0, h0, l0); split_bf16(o1, h1, l1);
            size_t m = (size_t)(b * S_ + qbase + row) * D_ + col;
            *(__nv_bfloat162*)(g_athi + m) = __halves2bfloat162(h0, h1);
            *(__nv_bfloat162*)(g_atlo + m) = __halves2bfloat162(l0, l1);
        }
    }
}

// ------------------------- host launch ---------------------------------------
extern "C" void kernel_launch(void* const* d_in, const int* in_sizes, int n_in,
                              void* d_out, int out_size) {
    const float* x       = (const float*)d_in[0];
    const float* w_in    = (const float*)d_in[1];
    const float* b_in    = (const float*)d_in[2];
    const float* w_out   = (const float*)d_in[3];
    const float* b_out   = (const float*)d_in[4];
    const float* gate_w1 = (const float*)d_in[5];
    const float* gate_b1 = (const float*)d_in[6];
    const float* gate_w2 = (const float*)d_in[7];
    const float* gate_b2 = (const float*)d_in[8];
    float* out = (float*)d_out;

    cudaFuncSetAttribute(k_gate_qgemm, cudaFuncAttributeMaxDynamicSharedMemorySize, SMEM_GM);
    cudaFuncSetAttribute(k_kvgemm, cudaFuncAttributeMaxDynamicSharedMemorySize, SMEM_KV);
    cudaFuncSetAttribute(k_outgemm, cudaFuncAttributeMaxDynamicSharedMemorySize, SMEM_GM);
    cudaFuncSetAttribute(attn_mma, cudaFuncAttributeMaxDynamicSharedMemorySize, SMEM_AT2);

    // scale = log2(e) / sqrt(32): scores come out of QK^T in log2 domain
    const float qscale = 1.4426950408889634f * 0.17677669529663687f;

    // 1. fp32 -> bf16 hi/lo conversions (x, w_in, w_out, gate_w1)
    convert_all<<<(CONV_TOTAL + 255) / 256, 256>>>(
        (const float4*)x, (const float4*)w_in, (const float4*)w_out,
        (const float4*)gate_w1);

    // 2. gate GEMM (bf16x3 MMA, fused relu/dot/sigmoid) || Q projection GEMM
    k_gate_qgemm<<<GATE_BLOCKS + QG_BLOCKS, 256, SMEM_GM>>>(
        gate_b1, gate_w2, gate_b2, b_in, qscale);

    // 3. radix top-k -> rowmap
    k_topk<<<B_, 256>>>();

    // 4. K,V at kept rows (full-K-resident pipeline, single wave)
    k_kvgemm<<<dim3((2 * D_) / 64, (KV_ROWS + 63) / 64), 256, SMEM_KV>>>(b_in);

    // 5. attention: key-chunked online softmax, 4 CTAs/SM
    attn_mma<<<dim3(B_ * H_, S_ / 64), 128, SMEM_AT2>>>();

    // 6. out projection (fp32 out)
    k_outgemm<<<dim3(D_ / 64, ROWS / 64), 256, SMEM_GM>>>(b_out, out);
}

// round 16
// speedup vs baseline: 1.1486x; 1.0164x over previous
#include <cuda_runtime.h>
#include <cuda_bf16.h>
#include <math_constants.h>
#include <cstdint>

#define B_   4
#define S_   2048
#define D_   256
#define H_   8
#define HD_  32
#define KEEP 204            // int(2048 * 0.1)
#define KPAD 208            // padded keys in global V^T layout
#define ROWS (B_ * S_)      // 8192
#define KV_ROWS (B_ * KEEP) // 816
#define KD   256

// ------------------------- scratch (static device globals) -------------------
__device__ float g_importance[ROWS];
__device__ int   g_rowmap[KV_ROWS];
__device__ int   g_kvready;                 // topk completion counter
__device__ __nv_bfloat16 g_xhi[ROWS * D_],   g_xlo[ROWS * D_];
__device__ __nv_bfloat16 g_winhi[3 * D_ * D_], g_winlo[3 * D_ * D_];
__device__ __nv_bfloat16 g_wouthi[D_ * D_],  g_woutlo[D_ * D_];
__device__ __nv_bfloat16 g_gw1hi[64 * D_],   g_gw1lo[64 * D_];
__device__ __nv_bfloat16 g_qhi[ROWS * D_],   g_qlo[ROWS * D_];      // Q * log2e/sqrt(hd)
__device__ __nv_bfloat16 g_khi[KV_ROWS * D_], g_klo[KV_ROWS * D_];
__device__ __nv_bfloat16 g_vthi[B_ * H_ * HD_ * KPAD], g_vtlo[B_ * H_ * HD_ * KPAD];
__device__ __nv_bfloat16 g_athi[ROWS * D_],  g_atlo[ROWS * D_];

// ========================= helpers ============================================
__device__ __forceinline__ uint32_t smem_u32(const void* p) {
    uint32_t a;
    asm("{ .reg .u64 t; cvta.to.shared.u64 t, %1; cvt.u32.u64 %0, t; }" : "=r"(a) : "l"(p));
    return a;
}
__device__ __forceinline__ void ldsm_x4(uint32_t& r0, uint32_t& r1, uint32_t& r2,
                                        uint32_t& r3, uint32_t addr) {
    asm volatile("ldmatrix.sync.aligned.m8n8.x4.shared.b16 {%0,%1,%2,%3}, [%4];"
                 : "=r"(r0), "=r"(r1), "=r"(r2), "=r"(r3) : "r"(addr));
}
__device__ __forceinline__ void mma_bf16(float* c, const uint32_t* a, const uint32_t* b) {
    asm volatile("mma.sync.aligned.m16n8k16.row.col.f32.bf16.bf16.f32 "
                 "{%0,%1,%2,%3}, {%4,%5,%6,%7}, {%8,%9}, {%0,%1,%2,%3};"
                 : "+f"(c[0]), "+f"(c[1]), "+f"(c[2]), "+f"(c[3])
                 : "r"(a[0]), "r"(a[1]), "r"(a[2]), "r"(a[3]), "r"(b[0]), "r"(b[1]));
}
#define CP16(dst, src) \
    asm volatile("cp.async.cg.shared.global [%0], [%1], 16;" :: "r"(dst), "l"(src))
#define CP_COMMIT() asm volatile("cp.async.commit_group;" ::: "memory")
#define CP_WAIT(n)  asm volatile("cp.async.wait_group %0;" :: "n"(n) : "memory")

__device__ __forceinline__ void split_bf16(float v, __nv_bfloat16& h, __nv_bfloat16& l) {
    h = __float2bfloat16(v);
    l = __float2bfloat16(v - __bfloat162float(h));
}
__device__ __forceinline__ void pack_hi_lo(float a, float b, uint32_t& hi, uint32_t& lo) {
    __nv_bfloat16 ha, la, hb, lb;
    split_bf16(a, ha, la); split_bf16(b, hb, lb);
    __nv_bfloat162 th = __halves2bfloat162(ha, hb);
    __nv_bfloat162 tl = __halves2bfloat162(la, lb);
    hi = *(uint32_t*)&th; lo = *(uint32_t*)&tl;
}
// 2^x via FMA pipe (no MUFU): magic rounding + degree-5 poly, rel err < 3e-6
__device__ __forceinline__ float exp2_fast(float x) {
    x = fmaxf(x, -120.f);
    float t = x + 12582912.f;
    float f = x - (t - 12582912.f);
    uint32_t ti = __float_as_uint(t);
    float s = __uint_as_float((ti << 23) + 0x3F800000u);
    float p = 1.33335581e-3f;
    p = fmaf(p, f, 9.61812911e-3f);
    p = fmaf(p, f, 5.55041087e-2f);
    p = fmaf(p, f, 2.40226507e-1f);
    p = fmaf(p, f, 6.93147181e-1f);
    p = fmaf(p, f, 1.0f);
    return p * s;
}

// ========================= bf16x3 GEMM body (64x64 tile, 3-stage) =============
// modes: 0 fp32 out; 1 (acc+bias)*scale -> bf16 hi/lo; 3 gate epilogue
#define GKP 80
#define G_AHI 0
#define G_ALO 5120
#define G_BHI 10240
#define G_BLO 15360
#define G_STAGE 20480
#define SMEM_GM (3 * G_STAGE)                    // 61440 B
#define SMEM_KV (8 * G_STAGE)                    // 163840 B (full-K resident)

__device__ __forceinline__ void gemm_body(
    int bx, int by, char* smem,
    const __nv_bfloat16* __restrict__ Ahi, const __nv_bfloat16* __restrict__ Alo,
    const __nv_bfloat16* __restrict__ Bhi, const __nv_bfloat16* __restrict__ Blo,
    const float* __restrict__ bias, int M, int N, int mode, float scale,
    float* __restrict__ Cf, __nv_bfloat16* __restrict__ Chi, __nv_bfloat16* __restrict__ Clo,
    const float* __restrict__ gw2, const float* __restrict__ gb2) {
    uint32_t sb = smem_u32(smem);
    int tid = threadIdx.x, wid = tid >> 5, lane = tid & 31;
    int rowBase = by * 64, colBase = bx * 64;
    int warp_m = (wid >> 2) * 32;
    int warp_n = (wid & 3) * 16;

    int ra = tid >> 2, ca = tid & 3;
    int gar = (rowBase + ra < M) ? (rowBase + ra) : 0;
    const __nv_bfloat16* sAh = Ahi + (size_t)gar * KD + ca * 8;
    const __nv_bfloat16* sAl = Alo + (size_t)gar * KD + ca * 8;
    const __nv_bfloat16* sBh = Bhi + (size_t)(colBase + ra) * KD + ca * 8;
    const __nv_bfloat16* sBl = Blo + (size_t)(colBase + ra) * KD + ca * 8;
    uint32_t dd = sb + (uint32_t)(ra * GKP + ca * 16);

    auto issue = [&](int kt, int st) {
        uint32_t so = (uint32_t)st * G_STAGE;
        int ko = kt * 32;
        CP16(dd + so + G_AHI, sAh + ko);
        CP16(dd + so + G_ALO, sAl + ko);
        CP16(dd + so + G_BHI, sBh + ko);
        CP16(dd + so + G_BLO, sBl + ko);
        CP_COMMIT();
    };

    uint32_t arel[2];
    #pragma unroll
    for (int mf = 0; mf < 2; mf++)
        arel[mf] = (uint32_t)((warp_m + mf * 16 + (lane & 15)) * GKP + (lane >> 4) * 16);
    int bg = lane >> 3, br = lane & 7;
    uint32_t brel = (uint32_t)((warp_n + (bg >> 1) * 8 + br) * GKP + (bg & 1) * 16);

    float acc[2][2][4] = {};

    issue(0, 0);
    issue(1, 1);
    #pragma unroll 1
    for (int kt = 0; kt < 8; kt++) {
        CP_WAIT(1);
        __syncthreads();
        if (kt < 6) issue(kt + 2, (kt + 2) % 3);
        uint32_t base = sb + (uint32_t)((kt % 3) * G_STAGE);
        #pragma unroll
        for (int kc = 0; kc < 2; kc++) {
            uint32_t koff = (uint32_t)kc * 32;
            uint32_t bh[2][2], bl[2][2];
            ldsm_x4(bh[0][0], bh[0][1], bh[1][0], bh[1][1], base + G_BHI + brel + koff);
            ldsm_x4(bl[0][0], bl[0][1], bl[1][0], bl[1][1], base + G_BLO + brel + koff);
            #pragma unroll
            for (int mf = 0; mf < 2; mf++) {
                uint32_t ah[4], al[4];
                ldsm_x4(ah[0], ah[1], ah[2], ah[3], base + G_AHI + arel[mf] + koff);
                ldsm_x4(al[0], al[1], al[2], al[3], base + G_ALO + arel[mf] + koff);
                #pragma unroll
                for (int nf = 0; nf < 2; nf++) {
                    mma_bf16(acc[mf][nf], ah, bh[nf]);
                    mma_bf16(acc[mf][nf], ah, bl[nf]);
                    mma_bf16(acc[mf][nf], al, bh[nf]);
                }
            }
        }
    }

    if (mode == 3) {
        __syncthreads();
        float* red = (float*)smem;
        float part[2][2];
        #pragma unroll
        for (int mf = 0; mf < 2; mf++)
            #pragma unroll
            for (int half = 0; half < 2; half++) part[mf][half] = 0.f;
        #pragma unroll
        for (int nf = 0; nf < 2; nf++) {
            #pragma unroll
            for (int j = 0; j < 2; j++) {
                int col = warp_n + nf * 8 + (lane & 3) * 2 + j;
                float b1v = __ldg(bias + col);
                float w2v = __ldg(gw2 + col);
                #pragma unroll
                for (int mf = 0; mf < 2; mf++)
                    #pragma unroll
                    for (int half = 0; half < 2; half++)
                        part[mf][half] += fmaxf(acc[mf][nf][half * 2 + j] + b1v, 0.f) * w2v;
            }
        }
        #pragma unroll
        for (int mf = 0; mf < 2; mf++)
            #pragma unroll
            for (int half = 0; half < 2; half++) {
                float p = part[mf][half];
                p += __shfl_xor_sync(0xffffffffu, p, 1);
                p += __shfl_xor_sync(0xffffffffu, p, 2);
                if ((lane & 3) == 0) {
                    int row = warp_m + mf * 16 + (lane >> 2) + half * 8;
                    red[row * 4 + (wid & 3)] = p;
                }
            }
        __syncthreads();
        if (tid < 64) {
            float s = red[tid * 4] + red[tid * 4 + 1] + red[tid * 4 + 2] + red[tid * 4 + 3];
            g_importance[rowBase + tid] = 1.f / (1.f + expf(-(s + gb2[0])));
        }
        return;
    }

    #pragma unroll
    for (int mf = 0; mf < 2; mf++) {
        #pragma unroll
        for (int nf = 0; nf < 2; nf++) {
            int n = colBase + warp_n + nf * 8 + (lane & 3) * 2;
            float b0 = __ldg(bias + n), b1 = __ldg(bias + n + 1);
            #pragma unroll
            for (int half = 0; half < 2; half++) {
                int m = rowBase + warp_m + mf * 16 + (lane >> 2) + half * 8;
                if (m >= M) continue;
                float o0 = acc[mf][nf][half * 2 + 0] + b0;
                float o1 = acc[mf][nf][half * 2 + 1] + b1;
                if (mode == 0) {
                    *(float2*)(Cf + (size_t)m * N + n) = make_float2(o0, o1);
                } else {
                    o0 *= scale; o1 *= scale;
                    __nv_bfloat16 h0, l0, h1, l1;
                    split_bf16(o0, h0, l0); split_bf16(o1, h1, l1);
                    *(__nv_bfloat162*)(Chi + (size_t)m * N + n) = __halves2bfloat162(h0, h1);
                    *(__nv_bfloat162*)(Clo + (size_t)m * N + n) = __halves2bfloat162(l0, l1);
                }
            }
        }
    }
}

// ========== KV GEMM body: B prefetched before rowmap spin, full-K resident ===
__device__ __forceinline__ void gemm_kv_body(
    int bx, int by, char* smem, const float* __restrict__ bias) {
    uint32_t sb = smem_u32(smem);
    int tid = threadIdx.x, wid = tid >> 5, lane = tid & 31;
    int rowBase = by * 64, colBase = bx * 64;
    int warp_m = (wid >> 2) * 32;
    int warp_n = (wid & 3) * 16;
    const __nv_bfloat16* Bhi = g_winhi + D_ * D_;
    const __nv_bfloat16* Blo = g_winlo + D_ * D_;

    int ra = tid >> 2, ca = tid & 3;
    const __nv_bfloat16* sBh = Bhi + (size_t)(colBase + ra) * KD + ca * 8;
    const __nv_bfloat16* sBl = Blo + (size_t)(colBase + ra) * KD + ca * 8;
    uint32_t dd = sb + (uint32_t)(ra * GKP + ca * 16);

    // ---- B tiles first (independent of rowmap): overlaps topk ----
    #pragma unroll
    for (int kt = 0; kt < 8; kt++) {
        uint32_t so = (uint32_t)kt * G_STAGE;
        int ko = kt * 32;
        CP16(dd + so + G_BHI, sBh + ko);
        CP16(dd + so + G_BLO, sBl + ko);
    }
    CP_COMMIT();

    // ---- wait for topk (all blocks wave-1 resident -> no deadlock) ----
    if (tid == 0) {
        while (*(volatile int*)&g_kvready < B_) {}
    }
    __syncthreads();
    __threadfence();

    // ---- A tiles (gathered rows) ----
    int gar = (rowBase + ra < KV_ROWS) ? g_rowmap[rowBase + ra] : 0;
    const __nv_bfloat16* sAh = g_xhi + (size_t)gar * KD + ca * 8;
    const __nv_bfloat16* sAl = g_xlo + (size_t)gar * KD + ca * 8;
    #pragma unroll
    for (int kt = 0; kt < 8; kt++) {
        uint32_t so = (uint32_t)kt * G_STAGE;
        int ko = kt * 32;
        CP16(dd + so + G_AHI, sAh + ko);
        CP16(dd + so + G_ALO, sAl + ko);
    }
    CP_COMMIT();
    CP_WAIT(0);
    __syncthreads();

    uint32_t arel[2];
    #pragma unroll
    for (int mf = 0; mf < 2; mf++)
        arel[mf] = (uint32_t)((warp_m + mf * 16 + (lane & 15)) * GKP + (lane >> 4) * 16);
    int bg = lane >> 3, br = lane & 7;
    uint32_t brel = (uint32_t)((warp_n + (bg >> 1) * 8 + br) * GKP + (bg & 1) * 16);

    float acc[2][2][4] = {};

    #pragma unroll
    for (int kt = 0; kt < 8; kt++) {
        uint32_t base = sb + (uint32_t)(kt * G_STAGE);
        #pragma unroll
        for (int kc = 0; kc < 2; kc++) {
            uint32_t koff = (uint32_t)kc * 32;
            uint32_t bh[2][2], bl[2][2];
            ldsm_x4(bh[0][0], bh[0][1], bh[1][0], bh[1][1], base + G_BHI + brel + koff);
            ldsm_x4(bl[0][0], bl[0][1], bl[1][0], bl[1][1], base + G_BLO + brel + koff);
            #pragma unroll
            for (int mf = 0; mf < 2; mf++) {
                uint32_t ah[4], al[4];
                ldsm_x4(ah[0], ah[1], ah[2], ah[3], base + G_AHI + arel[mf] + koff);
                ldsm_x4(al[0], al[1], al[2], al[3], base + G_ALO + arel[mf] + koff);
                #pragma unroll
                for (int nf = 0; nf < 2; nf++) {
                    mma_bf16(acc[mf][nf], ah, bh[nf]);
                    mma_bf16(acc[mf][nf], ah, bl[nf]);
                    mma_bf16(acc[mf][nf], al, bh[nf]);
                }
            }
        }
    }

    #pragma unroll
    for (int mf = 0; mf < 2; mf++) {
        #pragma unroll
        for (int nf = 0; nf < 2; nf++) {
            int n = colBase + warp_n + nf * 8 + (lane & 3) * 2;
            float b0 = __ldg(bias + n), b1 = __ldg(bias + n + 1);
            #pragma unroll
            for (int half = 0; half < 2; half++) {
                int m = rowBase + warp_m + mf * 16 + (lane >> 2) + half * 8;
                if (m >= KV_ROWS) continue;
                float o0 = acc[mf][nf][half * 2 + 0] + b0;
                float o1 = acc[mf][nf][half * 2 + 1] + b1;
                __nv_bfloat16 h0, l0, h1, l1;
                split_bf16(o0, h0, l0); split_bf16(o1, h1, l1);
                if (n < 256) {
                    *(__nv_bfloat162*)(g_khi + (size_t)m * 256 + n) = __halves2bfloat162(h0, h1);
                    *(__nv_bfloat162*)(g_klo + (size_t)m * 256 + n) = __halves2bfloat162(l0, l1);
                } else {
                    int bb = m / KEEP, j = m - bb * KEEP;
                    int hh = (n - 256) >> 5, dd2 = (n - 256) & 31;
                    size_t i0 = ((size_t)(bb * H_ + hh) * HD_ + dd2) * KPAD + j;
                    size_t i1 = ((size_t)(bb * H_ + hh) * HD_ + dd2 + 1) * KPAD + j;
                    g_vthi[i0] = h0; g_vtlo[i0] = l0;
                    g_vthi[i1] = h1; g_vtlo[i1] = l1;
                }
            }
        }
    }
}

// ========================= launch 1: all conversions (16B stores) ============
#define CN1 (ROWS * D_ / 8)       // counts in float4-PAIRS (8 floats)
#define CN2 (3 * D_ * D_ / 8)
#define CN3 (D_ * D_ / 8)
#define CN4 (64 * D_ / 8)
#define CONV_TOTAL (CN1 + CN2 + CN3 + CN4)

__global__ void convert_all(const float4* __restrict__ x,
                            const float4* __restrict__ w_in,
                            const float4* __restrict__ w_out,
                            const float4* __restrict__ gw1) {
    int i = blockIdx.x * blockDim.x + threadIdx.x;
    if (i == 0) g_kvready = 0;            // reset flag for this replay
    const float4* src;
    uint4 *hi, *lo;
    int off;
    if (i < CN1) {
        src = x; hi = (uint4*)g_xhi; lo = (uint4*)g_xlo; off = i;
    } else if (i < CN1 + CN2) {
        src = w_in; hi = (uint4*)g_winhi; lo = (uint4*)g_winlo; off = i - CN1;
    } else if (i < CN1 + CN2 + CN3) {
        src = w_out; hi = (uint4*)g_wouthi; lo = (uint4*)g_woutlo; off = i - CN1 - CN2;
    } else if (i < CONV_TOTAL) {
        src = gw1; hi = (uint4*)g_gw1hi; lo = (uint4*)g_gw1lo; off = i - CN1 - CN2 - CN3;
    } else return;
    float4 v0 = src[2 * off], v1 = src[2 * off + 1];
    uint32_t h[4], l[4];
    pack_hi_lo(v0.x, v0.y, h[0], l[0]);
    pack_hi_lo(v0.z, v0.w, h[1], l[1]);
    pack_hi_lo(v1.x, v1.y, h[2], l[2]);
    pack_hi_lo(v1.z, v1.w, h[3], l[3]);
    hi[off] = make_uint4(h[0], h[1], h[2], h[3]);
    lo[off] = make_uint4(l[0], l[1], l[2], l[3]);
}

// ========================= launch 2: gate MMA || Q GEMM =======================
#define GATE_BLOCKS (ROWS / 64)       // 128
#define QG_BLOCKS (4 * (ROWS / 64))   // 512

__global__ __launch_bounds__(256) void k_gate_qgemm(
    const float* __restrict__ gb1, const float* __restrict__ gw2,
    const float* __restrict__ gb2,
    const float* __restrict__ b_in, float qscale) {
    extern __shared__ char smem[];
    if (blockIdx.x < GATE_BLOCKS) {
        gemm_body(0, blockIdx.x, smem,
                  g_xhi, g_xlo, g_gw1hi, g_gw1lo,
                  gb1, ROWS, 64, 3, 1.f,
                  nullptr, nullptr, nullptr, gw2, gb2);
        return;
    }
    int g = blockIdx.x - GATE_BLOCKS;
    gemm_body(g & 3, g >> 2, smem,
              g_xhi, g_xlo, g_winhi, g_winlo,
              b_in, ROWS, D_, 1, qscale,
              nullptr, g_qhi, g_qlo, nullptr, nullptr);
}

// ========================= launch 3: topk + KV (fused, all wave-1) ===========
__device__ void topk_body(int b, char* smem) {
    uint32_t* bits = (uint32_t*)smem;
    int* hist   = (int*)(smem + 8192);
    int* eqlist = (int*)(smem + 9216);
    int* sc     = (int*)(smem + 10240);
    int t = threadIdx.x;
    for (int i = t; i < S_; i += 256)
        bits[i] = __float_as_uint(g_importance[b * S_ + i]);
    __syncthreads();

    uint32_t prefix = 0, prefmask = 0;
    int k_rem = KEEP;
    #pragma unroll
    for (int lev = 0; lev < 4; lev++) {
        int shift = 24 - lev * 8;
        hist[t] = 0;
        __syncthreads();
        for (int i = t; i < S_; i += 256) {
            uint32_t v = bits[i];
            if ((v & prefmask) == prefix) atomicAdd(&hist[(v >> shift) & 255], 1);
        }
        __syncthreads();
        if (t == 0) {
            int acc = 0, bin = 255;
            for (; bin > 0; bin--) {
                if (acc + hist[bin] >= k_rem) break;
                acc += hist[bin];
            }
            sc[0] = bin; sc[1] = acc;
        }
        __syncthreads();
        prefix |= ((uint32_t)sc[0]) << shift;
        prefmask |= (0xFFu << shift);
        k_rem -= sc[1];
        __syncthreads();
    }
    if (t == 0) { sc[2] = 0; sc[3] = 0; }
    __syncthreads();
    for (int i = t; i < S_; i += 256) {
        uint32_t v = bits[i];
        if (v > prefix) {
            int s = atomicAdd(&sc[2], 1);
            g_rowmap[b * KEEP + s] = b * S_ + i;
        } else if (v == prefix) {
            int s = atomicAdd(&sc[3], 1);
            if (s < 256) eqlist[s] = i;
        }
    }
    __syncthreads();
    int ne = min(sc[3], 256);
    if (t < ne) {
        int idx = eqlist[t], rank = 0;
        for (int j = 0; j < ne; j++) rank += (eqlist[j] < idx);
        if (rank < k_rem) g_rowmap[b * KEEP + sc[2] + rank] = b * S_ + idx;
    }
    __syncthreads();
    __threadfence();
    if (t == 0) atomicAdd(&g_kvready, 1);
}

__global__ __launch_bounds__(256) void k_topk_kv(const float* __restrict__ b_in) {
    extern __shared__ char smem[];
    if (blockIdx.x < B_) {
        topk_body(blockIdx.x, smem);
        return;
    }
    int g = blockIdx.x - B_;
    gemm_kv_body(g & 7, g >> 3, smem, b_in + D_);
}
#define TOPKKV_BLOCKS (B_ + 8 * 13)   // 108 <= 148 SMs: all wave-1 resident

// ========================= launch 5: out-proj GEMM ============================
__global__ __launch_bounds__(256) void k_outgemm(
    const float* __restrict__ b_out, float* __restrict__ out) {
    extern __shared__ char smem[];
    gemm_body(blockIdx.x, blockIdx.y, smem,
              g_athi, g_atlo, g_wouthi, g_woutlo,
              b_out, ROWS, D_, 0, 1.f,
              out, nullptr, nullptr, nullptr, nullptr);
}

// ========================= launch 4: MMA attention (key-chunked) ==============
#define PVS2 240
#define C_KHI 0
#define C_KLO 8960
#define C_VHI 17920
#define C_VLO (C_VHI + HD_ * PVS2)
#define SMEM_AT2 (C_VLO + HD_ * PVS2)      // 33280

__global__ __launch_bounds__(128, 4) void attn_mma() {
    extern __shared__ char smem[];
    uint32_t sb = smem_u32(smem);
    int tid = threadIdx.x, wid = tid >> 5, lane = tid & 31;
    int b = blockIdx.x >> 3, h = blockIdx.x & 7;
    int qbase = blockIdx.y * 64;
    int warp_m = wid * 16;
    int bg = lane >> 3, br = lane & 7;

    int qrow = qbase + warp_m + (lane >> 2);
    size_t q0 = (size_t)(b * S_ + qrow) * D_ + h * HD_ + (lane & 3) * 2;
    size_t q1 = q0 + 8 * (size_t)D_;
    uint32_t aqh[2][4], aql[2][4];
    #pragma unroll
    for (int ks = 0; ks < 2; ks++) {
        aqh[ks][0] = *(const uint32_t*)(g_qhi + q0 + ks * 16);
        aqh[ks][1] = *(const uint32_t*)(g_qhi + q1 + ks * 16);
        aqh[ks][2] = *(const uint32_t*)(g_qhi + q0 + 8 + ks * 16);
        aqh[ks][3] = *(const uint32_t*)(g_qhi + q1 + 8 + ks * 16);
        aql[ks][0] = *(const uint32_t*)(g_qlo + q0 + ks * 16);
        aql[ks][1] = *(const uint32_t*)(g_qlo + q1 + ks * 16);
        aql[ks][2] = *(const uint32_t*)(g_qlo + q0 + 8 + ks * 16);
        aql[ks][3] = *(const uint32_t*)(g_qlo + q1 + 8 + ks * 16);
    }

    uint32_t pbr0 = (uint32_t)(((bg >> 1) * 8 + br) * PVS2 + (bg & 1) * 16);
    uint32_t pbr1 = pbr0 + 16 * PVS2;

    float m0, m1, sum0 = 0.f, sum1 = 0.f;
    float oacc[4][4] = {};

    #pragma unroll
    for (int ch = 0; ch < 2; ch++) {
        int kb = ch * 112;
        if (ch) __syncthreads();
        for (int i = tid; i < 112 * 4; i += 128) {
            int j = i >> 2, c = i & 3;
            int gk = kb + j;
            uint4 vh = make_uint4(0, 0, 0, 0), vl = vh;
            if (gk < KEEP) {
                size_t off = (size_t)(b * KEEP + gk) * D_ + h * HD_ + c * 8;
                vh = *(const uint4*)(g_khi + off);
                vl = *(const uint4*)(g_klo + off);
            }
            *(uint4*)(smem + C_KHI + j * 80 + c * 16) = vh;
            *(uint4*)(smem + C_KLO + j * 80 + c * 16) = vl;
        }
        {
            int d = tid >> 2;
            size_t rowoff = ((size_t)(b * H_ + h) * HD_ + d) * KPAD + kb;
            for (int c = tid & 3; c < 14; c += 4) {
                int gkey = kb + c * 8;
                uint4 vh, vl;
                if (gkey + 8 <= KEEP) {
                    vh = *(const uint4*)(g_vthi + rowoff + c * 8);
                    vl = *(const uint4*)(g_vtlo + rowoff + c * 8);
                } else if (gkey < KEEP) {
                    uint2 th = *(const uint2*)(g_vthi + rowoff + c * 8);
                    uint2 tl = *(const uint2*)(g_vtlo + rowoff + c * 8);
                    vh = make_uint4(th.x, th.y, 0, 0);
                    vl = make_uint4(tl.x, tl.y, 0, 0);
                } else {
                    vh = make_uint4(0, 0, 0, 0); vl = vh;
                }
                *(uint4*)(smem + C_VHI + d * PVS2 + c * 16) = vh;
                *(uint4*)(smem + C_VLO + d * PVS2 + c * 16) = vl;
            }
        }
        __syncthreads();

        float sacc[14][4];
        #pragma unroll
        for (int t = 0; t < 14; t++)
            #pragma unroll
            for (int j = 0; j < 4; j++) sacc[t][j] = 0.f;

        #pragma unroll
        for (int nc = 0; nc < 7; nc++) {
            uint32_t brel = (uint32_t)((nc * 16 + (bg >> 1) * 8 + br) * 80 + (bg & 1) * 16);
            #pragma unroll
            for (int ks = 0; ks < 2; ks++) {
                uint32_t bh[2][2], bl[2][2];
                ldsm_x4(bh[0][0], bh[0][1], bh[1][0], bh[1][1], sb + C_KHI + brel + ks * 32);
                ldsm_x4(bl[0][0], bl[0][1], bl[1][0], bl[1][1], sb + C_KLO + brel + ks * 32);
                #pragma unroll
                for (int nf = 0; nf < 2; nf++) {
                    mma_bf16(sacc[nc * 2 + nf], aqh[ks], bh[nf]);
                    mma_bf16(sacc[nc * 2 + nf], aql[ks], bh[nf]);
                    mma_bf16(sacc[nc * 2 + nf], aqh[ks], bl[nf]);
                }
            }
        }

        if (ch == 1) {
            if ((lane & 3) >= 2) {
                sacc[11][0] = -1e30f; sacc[11][1] = -1e30f;
                sacc[11][2] = -1e30f; sacc[11][3] = -1e30f;
            }
            #pragma unroll
            for (int t = 12; t < 14; t++) {
                sacc[t][0] = -1e30f; sacc[t][1] = -1e30f;
                sacc[t][2] = -1e30f; sacc[t][3] = -1e30f;
            }
        }

        float cx0 = -1e30f, cx1 = -1e30f;
        #pragma unroll
        for (int t = 0; t < 14; t++) {
            cx0 = fmaxf(cx0, fmaxf(sacc[t][0], sacc[t][1]));
            cx1 = fmaxf(cx1, fmaxf(sacc[t][2], sacc[t][3]));
        }
        cx0 = fmaxf(cx0, __shfl_xor_sync(0xffffffffu, cx0, 1));
        cx0 = fmaxf(cx0, __shfl_xor_sync(0xffffffffu, cx0, 2));
        cx1 = fmaxf(cx1, __shfl_xor_sync(0xffffffffu, cx1, 1));
        cx1 = fmaxf(cx1, __shfl_xor_sync(0xffffffffu, cx1, 2));
        if (ch == 0) {
            m0 = cx0; m1 = cx1;
        } else {
            float nm0 = fmaxf(m0, cx0), nm1 = fmaxf(m1, cx1);
            float c0 = exp2_fast(m0 - nm0), c1 = exp2_fast(m1 - nm1);
            sum0 *= c0; sum1 *= c1;
            #pragma unroll
            for (int nf = 0; nf < 4; nf++) {
                oacc[nf][0] *= c0; oacc[nf][1] *= c0;
                oacc[nf][2] *= c1; oacc[nf][3] *= c1;
            }
            m0 = nm0; m1 = nm1;
        }

        #pragma unroll
        for (int t = 0; t < 14; t++) {
            sacc[t][0] = exp2_fast(sacc[t][0] - m0); sum0 += sacc[t][0];
            sacc[t][1] = exp2_fast(sacc[t][1] - m0); sum0 += sacc[t][1];
            sacc[t][2] = exp2_fast(sacc[t][2] - m1); sum1 += sacc[t][2];
            sacc[t][3] = exp2_fast(sacc[t][3] - m1); sum1 += sacc[t][3];
        }

        #pragma unroll
        for (int ks = 0; ks < 7; ks++) {
            uint32_t ph[4], pl[4];
            pack_hi_lo(sacc[2*ks][0],   sacc[2*ks][1],   ph[0], pl[0]);
            pack_hi_lo(sacc[2*ks][2],   sacc[2*ks][3],   ph[1], pl[1]);
            pack_hi_lo(sacc[2*ks+1][0], sacc[2*ks+1][1], ph[2], pl[2]);
            pack_hi_lo(sacc[2*ks+1][2], sacc[2*ks+1][3], ph[3], pl[3]);
            uint32_t koff = (uint32_t)ks * 32;
            uint32_t vh[4][2], vl[4][2];
            ldsm_x4(vh[0][0], vh[0][1], vh[1][0], vh[1][1], sb + C_VHI + pbr0 + koff);
            ldsm_x4(vh[2][0], vh[2][1], vh[3][0], vh[3][1], sb + C_VHI + pbr1 + koff);
            ldsm_x4(vl[0][0], vl[0][1], vl[1][0], vl[1][1], sb + C_VLO + pbr0 + koff);
            ldsm_x4(vl[2][0], vl[2][1], vl[3][0], vl[3][1], sb + C_VLO + pbr1 + koff);
            #pragma unroll
            for (int nf = 0; nf < 4; nf++) {
                mma_bf16(oacc[nf], ph, vh[nf]);
                mma_bf16(oacc[nf], pl, vh[nf]);
                mma_bf16(oacc[nf], ph, vl[nf]);
            }
        }
    }

    sum0 += __shfl_xor_sync(0xffffffffu, sum0, 1);
    sum0 += __shfl_xor_sync(0xffffffffu, sum0, 2);
    sum1 += __shfl_xor_sync(0xffffffffu, sum1, 1);
    sum1 += __shfl_xor_sync(0xffffffffu, sum1, 2);
    float inv0 = 1.f / sum0, inv1 = 1.f / sum1;

    #pragma unroll
    for (int nf = 0; nf < 4; nf++) {
        int col = h * HD_ + nf * 8 + (lane & 3) * 2;
        #pragma unroll
        for (int half = 0; half < 2; half++) {
            int row = warp_m + (lane >> 2) + half * 8;
            float il = half ? inv1 : inv0;
            float o0 = oacc[nf][half * 2 + 0] * il;
            float o1 = oacc[nf][half * 2 + 1] * il;
            __nv_bfloat16 h0, l0, h1, l1;
            split_bf16(o0, h0, l0); split_bf16(o1, h1, l1);
            size_t m = (size_t)(b * S_ + qbase + row) * D_ + col;
            *(__nv_bfloat162*)(g_athi + m) = __halves2bfloat162(h0, h1);
            *(__nv_bfloat162*)(g_atlo + m) = __halves2bfloat162(l0, l1);
        }
    }
}

// ------------------------- host launch ---------------------------------------
extern "C" void kernel_launch(void* const* d_in, const int* in_sizes, int n_in,
                              void* d_out, int out_size) {
    const float* x       = (const float*)d_in[0];
    const float* w_in    = (const float*)d_in[1];
    const float* b_in    = (const float*)d_in[2];
    const float* w_out   = (const float*)d_in[3];
    const float* b_out   = (const float*)d_in[4];
    const float* gate_w1 = (const float*)d_in[5];
    const float* gate_b1 = (const float*)d_in[6];
    const float* gate_w2 = (const float*)d_in[7];
    const float* gate_b2 = (const float*)d_in[8];
    float* out = (float*)d_out;

    cudaFuncSetAttribute(k_gate_qgemm, cudaFuncAttributeMaxDynamicSharedMemorySize, SMEM_GM);
    cudaFuncSetAttribute(k_topk_kv, cudaFuncAttributeMaxDynamicSharedMemorySize, SMEM_KV);
    cudaFuncSetAttribute(k_outgemm, cudaFuncAttributeMaxDynamicSharedMemorySize, SMEM_GM);
    cudaFuncSetAttribute(attn_mma, cudaFuncAttributeMaxDynamicSharedMemorySize, SMEM_AT2);

    // scale = log2(e) / sqrt(32): scores come out of QK^T in log2 domain
    const float qscale = 1.4426950408889634f * 0.17677669529663687f;

    // 1. fp32 -> bf16 hi/lo conversions (16B stores) + flag reset
    convert_all<<<(CONV_TOTAL + 255) / 256, 256>>>(
        (const float4*)x, (const float4*)w_in, (const float4*)w_out,
        (const float4*)gate_w1);

    // 2. gate GEMM (bf16x3 MMA, fused relu/dot/sigmoid) || Q projection GEMM
    k_gate_qgemm<<<GATE_BLOCKS + QG_BLOCKS, 256, SMEM_GM>>>(
        gate_b1, gate_w2, gate_b2, b_in, qscale);

    // 3. topk (4 blocks) + KV GEMM (104 blocks, B-prefetch before rowmap spin)
    k_topk_kv<<<TOPKKV_BLOCKS, 256, SMEM_KV>>>(b_in);

    // 4. attention: key-chunked online softmax, 4 CTAs/SM
    attn_mma<<<dim3(B_ * H_, S_ / 64), 128, SMEM_AT2>>>();

    // 5. out projection (fp32 out)
    k_outgemm<<<dim3(D_ / 64, ROWS / 64), 256, SMEM_GM>>>(b_out, out);
}

// round 17
// speedup vs baseline: 1.1578x; 1.0080x over previous
#include <cuda_runtime.h>
#include <cuda_bf16.h>
#include <math_constants.h>
#include <cstdint>

#define B_   4
#define S_   2048
#define D_   256
#define H_   8
#define HD_  32
#define KEEP 204            // int(2048 * 0.1)
#define KPAD 208            // padded keys in global V^T layout
#define ROWS (B_ * S_)      // 8192
#define KV_ROWS (B_ * KEEP) // 816
#define KD   256

// ------------------------- scratch (static device globals) -------------------
__device__ float g_importance[ROWS];
__device__ int   g_rowmap[KV_ROWS];
__device__ int   g_kvready;                 // topk completion counter
__device__ __nv_bfloat16 g_xhi[ROWS * D_],   g_xlo[ROWS * D_];
__device__ __nv_bfloat16 g_winhi[3 * D_ * D_], g_winlo[3 * D_ * D_];
__device__ __nv_bfloat16 g_wouthi[D_ * D_],  g_woutlo[D_ * D_];
__device__ __nv_bfloat16 g_gw1hi[64 * D_],   g_gw1lo[64 * D_];
__device__ __nv_bfloat16 g_qhi[ROWS * D_],   g_qlo[ROWS * D_];      // Q * log2e/sqrt(hd)
__device__ __nv_bfloat16 g_khi[KV_ROWS * D_];                        // K as bf16 (hi only)
__device__ __nv_bfloat16 g_vthi[B_ * H_ * HD_ * KPAD], g_vtlo[B_ * H_ * HD_ * KPAD];
__device__ __nv_bfloat16 g_athi[ROWS * D_],  g_atlo[ROWS * D_];

// ========================= helpers ============================================
__device__ __forceinline__ uint32_t smem_u32(const void* p) {
    uint32_t a;
    asm("{ .reg .u64 t; cvta.to.shared.u64 t, %1; cvt.u32.u64 %0, t; }" : "=r"(a) : "l"(p));
    return a;
}
__device__ __forceinline__ void ldsm_x4(uint32_t& r0, uint32_t& r1, uint32_t& r2,
                                        uint32_t& r3, uint32_t addr) {
    asm volatile("ldmatrix.sync.aligned.m8n8.x4.shared.b16 {%0,%1,%2,%3}, [%4];"
                 : "=r"(r0), "=r"(r1), "=r"(r2), "=r"(r3) : "r"(addr));
}
__device__ __forceinline__ void mma_bf16(float* c, const uint32_t* a, const uint32_t* b) {
    asm volatile("mma.sync.aligned.m16n8k16.row.col.f32.bf16.bf16.f32 "
                 "{%0,%1,%2,%3}, {%4,%5,%6,%7}, {%8,%9}, {%0,%1,%2,%3};"
                 : "+f"(c[0]), "+f"(c[1]), "+f"(c[2]), "+f"(c[3])
                 : "r"(a[0]), "r"(a[1]), "r"(a[2]), "r"(a[3]), "r"(b[0]), "r"(b[1]));
}
#define CP16(dst, src) \
    asm volatile("cp.async.cg.shared.global [%0], [%1], 16;" :: "r"(dst), "l"(src))
#define CP_COMMIT() asm volatile("cp.async.commit_group;" ::: "memory")
#define CP_WAIT(n)  asm volatile("cp.async.wait_group %0;" :: "n"(n) : "memory")

__device__ __forceinline__ void split_bf16(float v, __nv_bfloat16& h, __nv_bfloat16& l) {
    h = __float2bfloat16(v);
    l = __float2bfloat16(v - __bfloat162float(h));
}
__device__ __forceinline__ void pack_hi_lo(float a, float b, uint32_t& hi, uint32_t& lo) {
    __nv_bfloat16 ha, la, hb, lb;
    split_bf16(a, ha, la); split_bf16(b, hb, lb);
    __nv_bfloat162 th = __halves2bfloat162(ha, hb);
    __nv_bfloat162 tl = __halves2bfloat162(la, lb);
    hi = *(uint32_t*)&th; lo = *(uint32_t*)&tl;
}
// 2^x via FMA pipe (no MUFU): magic rounding + degree-5 poly, rel err < 3e-6
__device__ __forceinline__ float exp2_fast(float x) {
    x = fmaxf(x, -120.f);
    float t = x + 12582912.f;
    float f = x - (t - 12582912.f);
    uint32_t ti = __float_as_uint(t);
    float s = __uint_as_float((ti << 23) + 0x3F800000u);
    float p = 1.33335581e-3f;
    p = fmaf(p, f, 9.61812911e-3f);
    p = fmaf(p, f, 5.55041087e-2f);
    p = fmaf(p, f, 2.40226507e-1f);
    p = fmaf(p, f, 6.93147181e-1f);
    p = fmaf(p, f, 1.0f);
    return p * s;
}

// ========================= bf16x3 GEMM body (64x64 tile, 3-stage) =============
// modes: 0 fp32 out; 1 (acc+bias)*scale -> bf16 hi/lo; 3 gate epilogue
#define GKP 80
#define G_AHI 0
#define G_ALO 5120
#define G_BHI 10240
#define G_BLO 15360
#define G_STAGE 20480
#define SMEM_GM (3 * G_STAGE)                    // 61440 B
#define SMEM_KV (8 * G_STAGE)                    // 163840 B (full-K resident)

__device__ __forceinline__ void gemm_body(
    int bx, int by, char* smem,
    const __nv_bfloat16* __restrict__ Ahi, const __nv_bfloat16* __restrict__ Alo,
    const __nv_bfloat16* __restrict__ Bhi, const __nv_bfloat16* __restrict__ Blo,
    const float* __restrict__ bias, int M, int N, int mode, float scale,
    float* __restrict__ Cf, __nv_bfloat16* __restrict__ Chi, __nv_bfloat16* __restrict__ Clo,
    const float* __restrict__ gw2, const float* __restrict__ gb2) {
    uint32_t sb = smem_u32(smem);
    int tid = threadIdx.x, wid = tid >> 5, lane = tid & 31;
    int rowBase = by * 64, colBase = bx * 64;
    int warp_m = (wid >> 2) * 32;
    int warp_n = (wid & 3) * 16;

    int ra = tid >> 2, ca = tid & 3;
    int gar = (rowBase + ra < M) ? (rowBase + ra) : 0;
    const __nv_bfloat16* sAh = Ahi + (size_t)gar * KD + ca * 8;
    const __nv_bfloat16* sAl = Alo + (size_t)gar * KD + ca * 8;
    const __nv_bfloat16* sBh = Bhi + (size_t)(colBase + ra) * KD + ca * 8;
    const __nv_bfloat16* sBl = Blo + (size_t)(colBase + ra) * KD + ca * 8;
    uint32_t dd = sb + (uint32_t)(ra * GKP + ca * 16);

    auto issue = [&](int kt, int st) {
        uint32_t so = (uint32_t)st * G_STAGE;
        int ko = kt * 32;
        CP16(dd + so + G_AHI, sAh + ko);
        CP16(dd + so + G_ALO, sAl + ko);
        CP16(dd + so + G_BHI, sBh + ko);
        CP16(dd + so + G_BLO, sBl + ko);
        CP_COMMIT();
    };

    uint32_t arel[2];
    #pragma unroll
    for (int mf = 0; mf < 2; mf++)
        arel[mf] = (uint32_t)((warp_m + mf * 16 + (lane & 15)) * GKP + (lane >> 4) * 16);
    int bg = lane >> 3, br = lane & 7;
    uint32_t brel = (uint32_t)((warp_n + (bg >> 1) * 8 + br) * GKP + (bg & 1) * 16);

    float acc[2][2][4] = {};

    issue(0, 0);
    issue(1, 1);
    #pragma unroll 1
    for (int kt = 0; kt < 8; kt++) {
        CP_WAIT(1);
        __syncthreads();
        if (kt < 6) issue(kt + 2, (kt + 2) % 3);
        uint32_t base = sb + (uint32_t)((kt % 3) * G_STAGE);
        #pragma unroll
        for (int kc = 0; kc < 2; kc++) {
            uint32_t koff = (uint32_t)kc * 32;
            uint32_t bh[2][2], bl[2][2];
            ldsm_x4(bh[0][0], bh[0][1], bh[1][0], bh[1][1], base + G_BHI + brel + koff);
            ldsm_x4(bl[0][0], bl[0][1], bl[1][0], bl[1][1], base + G_BLO + brel + koff);
            #pragma unroll
            for (int mf = 0; mf < 2; mf++) {
                uint32_t ah[4], al[4];
                ldsm_x4(ah[0], ah[1], ah[2], ah[3], base + G_AHI + arel[mf] + koff);
                ldsm_x4(al[0], al[1], al[2], al[3], base + G_ALO + arel[mf] + koff);
                #pragma unroll
                for (int nf = 0; nf < 2; nf++) {
                    mma_bf16(acc[mf][nf], ah, bh[nf]);
                    mma_bf16(acc[mf][nf], ah, bl[nf]);
                    mma_bf16(acc[mf][nf], al, bh[nf]);
                }
            }
        }
    }

    if (mode == 3) {
        __syncthreads();
        float* red = (float*)smem;
        float part[2][2];
        #pragma unroll
        for (int mf = 0; mf < 2; mf++)
            #pragma unroll
            for (int half = 0; half < 2; half++) part[mf][half] = 0.f;
        #pragma unroll
        for (int nf = 0; nf < 2; nf++) {
            #pragma unroll
            for (int j = 0; j < 2; j++) {
                int col = warp_n + nf * 8 + (lane & 3) * 2 + j;
                float b1v = __ldg(bias + col);
                float w2v = __ldg(gw2 + col);
                #pragma unroll
                for (int mf = 0; mf < 2; mf++)
                    #pragma unroll
                    for (int half = 0; half < 2; half++)
                        part[mf][half] += fmaxf(acc[mf][nf][half * 2 + j] + b1v, 0.f) * w2v;
            }
        }
        #pragma unroll
        for (int mf = 0; mf < 2; mf++)
            #pragma unroll
            for (int half = 0; half < 2; half++) {
                float p = part[mf][half];
                p += __shfl_xor_sync(0xffffffffu, p, 1);
                p += __shfl_xor_sync(0xffffffffu, p, 2);
                if ((lane & 3) == 0) {
                    int row = warp_m + mf * 16 + (lane >> 2) + half * 8;
                    red[row * 4 + (wid & 3)] = p;
                }
            }
        __syncthreads();
        if (tid < 64) {
            float s = red[tid * 4] + red[tid * 4 + 1] + red[tid * 4 + 2] + red[tid * 4 + 3];
            g_importance[rowBase + tid] = 1.f / (1.f + expf(-(s + gb2[0])));
        }
        return;
    }

    #pragma unroll
    for (int mf = 0; mf < 2; mf++) {
        #pragma unroll
        for (int nf = 0; nf < 2; nf++) {
            int n = colBase + warp_n + nf * 8 + (lane & 3) * 2;
            float b0 = __ldg(bias + n), b1 = __ldg(bias + n + 1);
            #pragma unroll
            for (int half = 0; half < 2; half++) {
                int m = rowBase + warp_m + mf * 16 + (lane >> 2) + half * 8;
                if (m >= M) continue;
                float o0 = acc[mf][nf][half * 2 + 0] + b0;
                float o1 = acc[mf][nf][half * 2 + 1] + b1;
                if (mode == 0) {
                    *(float2*)(Cf + (size_t)m * N + n) = make_float2(o0, o1);
                } else {
                    o0 *= scale; o1 *= scale;
                    __nv_bfloat16 h0, l0, h1, l1;
                    split_bf16(o0, h0, l0); split_bf16(o1, h1, l1);
                    *(__nv_bfloat162*)(Chi + (size_t)m * N + n) = __halves2bfloat162(h0, h1);
                    *(__nv_bfloat162*)(Clo + (size_t)m * N + n) = __halves2bfloat162(l0, l1);
                }
            }
        }
    }
}

// ========== KV GEMM body: B prefetched before rowmap spin, full-K resident ===
__device__ __forceinline__ void gemm_kv_body(
    int bx, int by, char* smem, const float* __restrict__ bias) {
    uint32_t sb = smem_u32(smem);
    int tid = threadIdx.x, wid = tid >> 5, lane = tid & 31;
    int rowBase = by * 64, colBase = bx * 64;
    int warp_m = (wid >> 2) * 32;
    int warp_n = (wid & 3) * 16;
    const __nv_bfloat16* Bhi = g_winhi + D_ * D_;
    const __nv_bfloat16* Blo = g_winlo + D_ * D_;

    int ra = tid >> 2, ca = tid & 3;
    const __nv_bfloat16* sBh = Bhi + (size_t)(colBase + ra) * KD + ca * 8;
    const __nv_bfloat16* sBl = Blo + (size_t)(colBase + ra) * KD + ca * 8;
    uint32_t dd = sb + (uint32_t)(ra * GKP + ca * 16);

    // ---- B tiles first (independent of rowmap): overlaps topk ----
    #pragma unroll
    for (int kt = 0; kt < 8; kt++) {
        uint32_t so = (uint32_t)kt * G_STAGE;
        int ko = kt * 32;
        CP16(dd + so + G_BHI, sBh + ko);
        CP16(dd + so + G_BLO, sBl + ko);
    }
    CP_COMMIT();

    // ---- wait for topk (all blocks wave-1 resident -> no deadlock) ----
    if (tid == 0) {
        while (*(volatile int*)&g_kvready < B_) {}
    }
    __syncthreads();
    __threadfence();

    // ---- A tiles (gathered rows) ----
    int gar = (rowBase + ra < KV_ROWS) ? g_rowmap[rowBase + ra] : 0;
    const __nv_bfloat16* sAh = g_xhi + (size_t)gar * KD + ca * 8;
    const __nv_bfloat16* sAl = g_xlo + (size_t)gar * KD + ca * 8;
    #pragma unroll
    for (int kt = 0; kt < 8; kt++) {
        uint32_t so = (uint32_t)kt * G_STAGE;
        int ko = kt * 32;
        CP16(dd + so + G_AHI, sAh + ko);
        CP16(dd + so + G_ALO, sAl + ko);
    }
    CP_COMMIT();
    CP_WAIT(0);
    __syncthreads();

    uint32_t arel[2];
    #pragma unroll
    for (int mf = 0; mf < 2; mf++)
        arel[mf] = (uint32_t)((warp_m + mf * 16 + (lane & 15)) * GKP + (lane >> 4) * 16);
    int bg = lane >> 3, br = lane & 7;
    uint32_t brel = (uint32_t)((warp_n + (bg >> 1) * 8 + br) * GKP + (bg & 1) * 16);

    float acc[2][2][4] = {};

    #pragma unroll
    for (int kt = 0; kt < 8; kt++) {
        uint32_t base = sb + (uint32_t)(kt * G_STAGE);
        #pragma unroll
        for (int kc = 0; kc < 2; kc++) {
            uint32_t koff = (uint32_t)kc * 32;
            uint32_t bh[2][2], bl[2][2];
            ldsm_x4(bh[0][0], bh[0][1], bh[1][0], bh[1][1], base + G_BHI + brel + koff);
            ldsm_x4(bl[0][0], bl[0][1], bl[1][0], bl[1][1], base + G_BLO + brel + koff);
            #pragma unroll
            for (int mf = 0; mf < 2; mf++) {
                uint32_t ah[4], al[4];
                ldsm_x4(ah[0], ah[1], ah[2], ah[3], base + G_AHI + arel[mf] + koff);
                ldsm_x4(al[0], al[1], al[2], al[3], base + G_ALO + arel[mf] + koff);
                #pragma unroll
                for (int nf = 0; nf < 2; nf++) {
                    mma_bf16(acc[mf][nf], ah, bh[nf]);
                    mma_bf16(acc[mf][nf], ah, bl[nf]);
                    mma_bf16(acc[mf][nf], al, bh[nf]);
                }
            }
        }
    }

    #pragma unroll
    for (int mf = 0; mf < 2; mf++) {
        #pragma unroll
        for (int nf = 0; nf < 2; nf++) {
            int n = colBase + warp_n + nf * 8 + (lane & 3) * 2;
            float b0 = __ldg(bias + n), b1 = __ldg(bias + n + 1);
            #pragma unroll
            for (int half = 0; half < 2; half++) {
                int m = rowBase + warp_m + mf * 16 + (lane >> 2) + half * 8;
                if (m >= KV_ROWS) continue;
                float o0 = acc[mf][nf][half * 2 + 0] + b0;
                float o1 = acc[mf][nf][half * 2 + 1] + b1;
                if (n < 256) {
                    // K: bf16 hi only (attention QK uses 2-pass; K_lo unused)
                    *(__nv_bfloat162*)(g_khi + (size_t)m * 256 + n) =
                        __halves2bfloat162(__float2bfloat16(o0), __float2bfloat16(o1));
                } else {
                    __nv_bfloat16 h0, l0, h1, l1;
                    split_bf16(o0, h0, l0); split_bf16(o1, h1, l1);
                    int bb = m / KEEP, j = m - bb * KEEP;
                    int hh = (n - 256) >> 5, dd2 = (n - 256) & 31;
                    size_t i0 = ((size_t)(bb * H_ + hh) * HD_ + dd2) * KPAD + j;
                    size_t i1 = ((size_t)(bb * H_ + hh) * HD_ + dd2 + 1) * KPAD + j;
                    g_vthi[i0] = h0; g_vtlo[i0] = l0;
                    g_vthi[i1] = h1; g_vtlo[i1] = l1;
                }
            }
        }
    }
}

// ========================= launch 1: all conversions (16B stores) ============
#define CN1 (ROWS * D_ / 8)       // counts in float4-PAIRS (8 floats)
#define CN2 (3 * D_ * D_ / 8)
#define CN3 (D_ * D_ / 8)
#define CN4 (64 * D_ / 8)
#define CONV_TOTAL (CN1 + CN2 + CN3 + CN4)

__global__ void convert_all(const float4* __restrict__ x,
                            const float4* __restrict__ w_in,
                            const float4* __restrict__ w_out,
                            const float4* __restrict__ gw1) {
    int i = blockIdx.x * blockDim.x + threadIdx.x;
    if (i == 0) g_kvready = 0;            // reset flag for this replay
    const float4* src;
    uint4 *hi, *lo;
    int off;
    if (i < CN1) {
        src = x; hi = (uint4*)g_xhi; lo = (uint4*)g_xlo; off = i;
    } else if (i < CN1 + CN2) {
        src = w_in; hi = (uint4*)g_winhi; lo = (uint4*)g_winlo; off = i - CN1;
    } else if (i < CN1 + CN2 + CN3) {
        src = w_out; hi = (uint4*)g_wouthi; lo = (uint4*)g_woutlo; off = i - CN1 - CN2;
    } else if (i < CONV_TOTAL) {
        src = gw1; hi = (uint4*)g_gw1hi; lo = (uint4*)g_gw1lo; off = i - CN1 - CN2 - CN3;
    } else return;
    float4 v0 = src[2 * off], v1 = src[2 * off + 1];
    uint32_t h[4], l[4];
    pack_hi_lo(v0.x, v0.y, h[0], l[0]);
    pack_hi_lo(v0.z, v0.w, h[1], l[1]);
    pack_hi_lo(v1.x, v1.y, h[2], l[2]);
    pack_hi_lo(v1.z, v1.w, h[3], l[3]);
    hi[off] = make_uint4(h[0], h[1], h[2], h[3]);
    lo[off] = make_uint4(l[0], l[1], l[2], l[3]);
}

// ========================= launch 2: gate MMA || Q GEMM =======================
#define GATE_BLOCKS (ROWS / 64)       // 128
#define QG_BLOCKS (4 * (ROWS / 64))   // 512

__global__ __launch_bounds__(256) void k_gate_qgemm(
    const float* __restrict__ gb1, const float* __restrict__ gw2,
    const float* __restrict__ gb2,
    const float* __restrict__ b_in, float qscale) {
    extern __shared__ char smem[];
    if (blockIdx.x < GATE_BLOCKS) {
        gemm_body(0, blockIdx.x, smem,
                  g_xhi, g_xlo, g_gw1hi, g_gw1lo,
                  gb1, ROWS, 64, 3, 1.f,
                  nullptr, nullptr, nullptr, gw2, gb2);
        return;
    }
    int g = blockIdx.x - GATE_BLOCKS;
    gemm_body(g & 3, g >> 2, smem,
              g_xhi, g_xlo, g_winhi, g_winlo,
              b_in, ROWS, D_, 1, qscale,
              nullptr, g_qhi, g_qlo, nullptr, nullptr);
}

// ========================= launch 3: topk + KV (fused, all wave-1) ===========
__device__ void topk_body(int b, char* smem) {
    uint32_t* bits = (uint32_t*)smem;
    int* hist   = (int*)(smem + 8192);
    int* eqlist = (int*)(smem + 9216);
    int* sc     = (int*)(smem + 10240);
    int t = threadIdx.x;
    for (int i = t; i < S_; i += 256)
        bits[i] = __float_as_uint(g_importance[b * S_ + i]);
    __syncthreads();

    uint32_t prefix = 0, prefmask = 0;
    int k_rem = KEEP;
    #pragma unroll
    for (int lev = 0; lev < 4; lev++) {
        int shift = 24 - lev * 8;
        hist[t] = 0;
        __syncthreads();
        for (int i = t; i < S_; i += 256) {
            uint32_t v = bits[i];
            if ((v & prefmask) == prefix) atomicAdd(&hist[(v >> shift) & 255], 1);
        }
        __syncthreads();
        if (t == 0) {
            int acc = 0, bin = 255;
            for (; bin > 0; bin--) {
                if (acc + hist[bin] >= k_rem) break;
                acc += hist[bin];
            }
            sc[0] = bin; sc[1] = acc;
        }
        __syncthreads();
        prefix |= ((uint32_t)sc[0]) << shift;
        prefmask |= (0xFFu << shift);
        k_rem -= sc[1];
        __syncthreads();
    }
    if (t == 0) { sc[2] = 0; sc[3] = 0; }
    __syncthreads();
    for (int i = t; i < S_; i += 256) {
        uint32_t v = bits[i];
        if (v > prefix) {
            int s = atomicAdd(&sc[2], 1);
            g_rowmap[b * KEEP + s] = b * S_ + i;
        } else if (v == prefix) {
            int s = atomicAdd(&sc[3], 1);
            if (s < 256) eqlist[s] = i;
        }
    }
    __syncthreads();
    int ne = min(sc[3], 256);
    if (t < ne) {
        int idx = eqlist[t], rank = 0;
        for (int j = 0; j < ne; j++) rank += (eqlist[j] < idx);
        if (rank < k_rem) g_rowmap[b * KEEP + sc[2] + rank] = b * S_ + idx;
    }
    __syncthreads();
    __threadfence();
    if (t == 0) atomicAdd(&g_kvready, 1);
}

__global__ __launch_bounds__(256) void k_topk_kv(const float* __restrict__ b_in) {
    extern __shared__ char smem[];
    if (blockIdx.x < B_) {
        topk_body(blockIdx.x, smem);
        return;
    }
    int g = blockIdx.x - B_;
    gemm_kv_body(g & 7, g >> 3, smem, b_in + D_);
}
#define TOPKKV_BLOCKS (B_ + 8 * 13)   // 108 <= 148 SMs: all wave-1 resident

// ========================= launch 5: out-proj GEMM ============================
__global__ __launch_bounds__(256) void k_outgemm(
    const float* __restrict__ b_out, float* __restrict__ out) {
    extern __shared__ char smem[];
    gemm_body(blockIdx.x, blockIdx.y, smem,
              g_athi, g_atlo, g_wouthi, g_woutlo,
              b_out, ROWS, D_, 0, 1.f,
              out, nullptr, nullptr, nullptr, nullptr);
}

// ========================= launch 4: MMA attention (2-pass QK) ================
#define PVS2 240
#define C_KHI 0
#define C_VHI 8960                         // 112 * 80
#define C_VLO (C_VHI + HD_ * PVS2)         // 16640
#define SMEM_AT2 (C_VLO + HD_ * PVS2)      // 24320

__global__ __launch_bounds__(128, 4) void attn_mma() {
    extern __shared__ char smem[];
    uint32_t sb = smem_u32(smem);
    int tid = threadIdx.x, wid = tid >> 5, lane = tid & 31;
    int b = blockIdx.x >> 3, h = blockIdx.x & 7;
    int qbase = blockIdx.y * 64;
    int warp_m = wid * 16;
    int bg = lane >> 3, br = lane & 7;

    int qrow = qbase + warp_m + (lane >> 2);
    size_t q0 = (size_t)(b * S_ + qrow) * D_ + h * HD_ + (lane & 3) * 2;
    size_t q1 = q0 + 8 * (size_t)D_;
    uint32_t aqh[2][4], aql[2][4];
    #pragma unroll
    for (int ks = 0; ks < 2; ks++) {
        aqh[ks][0] = *(const uint32_t*)(g_qhi + q0 + ks * 16);
        aqh[ks][1] = *(const uint32_t*)(g_qhi + q1 + ks * 16);
        aqh[ks][2] = *(const uint32_t*)(g_qhi + q0 + 8 + ks * 16);
        aqh[ks][3] = *(const uint32_t*)(g_qhi + q1 + 8 + ks * 16);
        aql[ks][0] = *(const uint32_t*)(g_qlo + q0 + ks * 16);
        aql[ks][1] = *(const uint32_t*)(g_qlo + q1 + ks * 16);
        aql[ks][2] = *(const uint32_t*)(g_qlo + q0 + 8 + ks * 16);
        aql[ks][3] = *(const uint32_t*)(g_qlo + q1 + 8 + ks * 16);
    }

    uint32_t pbr0 = (uint32_t)(((bg >> 1) * 8 + br) * PVS2 + (bg & 1) * 16);
    uint32_t pbr1 = pbr0 + 16 * PVS2;

    float m0, m1, sum0 = 0.f, sum1 = 0.f;
    float oacc[4][4] = {};

    #pragma unroll
    for (int ch = 0; ch < 2; ch++) {
        int kb = ch * 112;
        if (ch) __syncthreads();
        // ---- K chunk (112 x 32, bf16 hi only) ----
        for (int i = tid; i < 112 * 4; i += 128) {
            int j = i >> 2, c = i & 3;
            int gk = kb + j;
            uint4 vh = make_uint4(0, 0, 0, 0);
            if (gk < KEEP) {
                size_t off = (size_t)(b * KEEP + gk) * D_ + h * HD_ + c * 8;
                vh = *(const uint4*)(g_khi + off);
            }
            *(uint4*)(smem + C_KHI + j * 80 + c * 16) = vh;
        }
        // ---- V^T chunk (32 x 112, hi/lo) ----
        {
            int d = tid >> 2;
            size_t rowoff = ((size_t)(b * H_ + h) * HD_ + d) * KPAD + kb;
            for (int c = tid & 3; c < 14; c += 4) {
                int gkey = kb + c * 8;
                uint4 vh, vl;
                if (gkey + 8 <= KEEP) {
                    vh = *(const uint4*)(g_vthi + rowoff + c * 8);
                    vl = *(const uint4*)(g_vtlo + rowoff + c * 8);
                } else if (gkey < KEEP) {
                    uint2 th = *(const uint2*)(g_vthi + rowoff + c * 8);
                    uint2 tl = *(const uint2*)(g_vtlo + rowoff + c * 8);
                    vh = make_uint4(th.x, th.y, 0, 0);
                    vl = make_uint4(tl.x, tl.y, 0, 0);
                } else {
                    vh = make_uint4(0, 0, 0, 0); vl = vh;
                }
                *(uint4*)(smem + C_VHI + d * PVS2 + c * 16) = vh;
                *(uint4*)(smem + C_VLO + d * PVS2 + c * 16) = vl;
            }
        }
        __syncthreads();

        // ---- scores: 2-pass (q_hi + q_lo) . k_hi ----
        float sacc[14][4];
        #pragma unroll
        for (int t = 0; t < 14; t++)
            #pragma unroll
            for (int j = 0; j < 4; j++) sacc[t][j] = 0.f;

        #pragma unroll
        for (int nc = 0; nc < 7; nc++) {
            uint32_t brel = (uint32_t)((nc * 16 + (bg >> 1) * 8 + br) * 80 + (bg & 1) * 16);
            #pragma unroll
            for (int ks = 0; ks < 2; ks++) {
                uint32_t bh[2][2];
                ldsm_x4(bh[0][0], bh[0][1], bh[1][0], bh[1][1], sb + C_KHI + brel + ks * 32);
                #pragma unroll
                for (int nf = 0; nf < 2; nf++) {
                    mma_bf16(sacc[nc * 2 + nf], aqh[ks], bh[nf]);
                    mma_bf16(sacc[nc * 2 + nf], aql[ks], bh[nf]);
                }
            }
        }

        if (ch == 1) {
            if ((lane & 3) >= 2) {
                sacc[11][0] = -1e30f; sacc[11][1] = -1e30f;
                sacc[11][2] = -1e30f; sacc[11][3] = -1e30f;
            }
            #pragma unroll
            for (int t = 12; t < 14; t++) {
                sacc[t][0] = -1e30f; sacc[t][1] = -1e30f;
                sacc[t][2] = -1e30f; sacc[t][3] = -1e30f;
            }
        }

        float cx0 = -1e30f, cx1 = -1e30f;
        #pragma unroll
        for (int t = 0; t < 14; t++) {
            cx0 = fmaxf(cx0, fmaxf(sacc[t][0], sacc[t][1]));
            cx1 = fmaxf(cx1, fmaxf(sacc[t][2], sacc[t][3]));
        }
        cx0 = fmaxf(cx0, __shfl_xor_sync(0xffffffffu, cx0, 1));
        cx0 = fmaxf(cx0, __shfl_xor_sync(0xffffffffu, cx0, 2));
        cx1 = fmaxf(cx1, __shfl_xor_sync(0xffffffffu, cx1, 1));
        cx1 = fmaxf(cx1, __shfl_xor_sync(0xffffffffu, cx1, 2));
        if (ch == 0) {
            m0 = cx0; m1 = cx1;
        } else {
            float nm0 = fmaxf(m0, cx0), nm1 = fmaxf(m1, cx1);
            float c0 = exp2_fast(m0 - nm0), c1 = exp2_fast(m1 - nm1);
            sum0 *= c0; sum1 *= c1;
            #pragma unroll
            for (int nf = 0; nf < 4; nf++) {
                oacc[nf][0] *= c0; oacc[nf][1] *= c0;
                oacc[nf][2] *= c1; oacc[nf][3] *= c1;
            }
            m0 = nm0; m1 = nm1;
        }

        #pragma unroll
        for (int t = 0; t < 14; t++) {
            sacc[t][0] = exp2_fast(sacc[t][0] - m0); sum0 += sacc[t][0];
            sacc[t][1] = exp2_fast(sacc[t][1] - m0); sum0 += sacc[t][1];
            sacc[t][2] = exp2_fast(sacc[t][2] - m1); sum1 += sacc[t][2];
            sacc[t][3] = exp2_fast(sacc[t][3] - m1); sum1 += sacc[t][3];
        }

        #pragma unroll
        for (int ks = 0; ks < 7; ks++) {
            uint32_t ph[4], pl[4];
            pack_hi_lo(sacc[2*ks][0],   sacc[2*ks][1],   ph[0], pl[0]);
            pack_hi_lo(sacc[2*ks][2],   sacc[2*ks][3],   ph[1], pl[1]);
            pack_hi_lo(sacc[2*ks+1][0], sacc[2*ks+1][1], ph[2], pl[2]);
            pack_hi_lo(sacc[2*ks+1][2], sacc[2*ks+1][3], ph[3], pl[3]);
            uint32_t koff = (uint32_t)ks * 32;
            uint32_t vh[4][2], vl[4][2];
            ldsm_x4(vh[0][0], vh[0][1], vh[1][0], vh[1][1], sb + C_VHI + pbr0 + koff);
            ldsm_x4(vh[2][0], vh[2][1], vh[3][0], vh[3][1], sb + C_VHI + pbr1 + koff);
            ldsm_x4(vl[0][0], vl[0][1], vl[1][0], vl[1][1], sb + C_VLO + pbr0 + koff);
            ldsm_x4(vl[2][0], vl[2][1], vl[3][0], vl[3][1], sb + C_VLO + pbr1 + koff);
            #pragma unroll
            for (int nf = 0; nf < 4; nf++) {
                mma_bf16(oacc[nf], ph, vh[nf]);
                mma_bf16(oacc[nf], pl, vh[nf]);
                mma_bf16(oacc[nf], ph, vl[nf]);
            }
        }
    }

    sum0 += __shfl_xor_sync(0xffffffffu, sum0, 1);
    sum0 += __shfl_xor_sync(0xffffffffu, sum0, 2);
    sum1 += __shfl_xor_sync(0xffffffffu, sum1, 1);
    sum1 += __shfl_xor_sync(0xffffffffu, sum1, 2);
    float inv0 = 1.f / sum0, inv1 = 1.f / sum1;

    #pragma unroll
    for (int nf = 0; nf < 4; nf++) {
        int col = h * HD_ + nf * 8 + (lane & 3) * 2;
        #pragma unroll
        for (int half = 0; half < 2; half++) {
            int row = warp_m + (lane >> 2) + half * 8;
            float il = half ? inv1 : inv0;
            float o0 = oacc[nf][half * 2 + 0] * il;
            float o1 = oacc[nf][half * 2 + 1] * il;
            __nv_bfloat16 h0, l0, h1, l1;
            split_bf16(o0, h0, l0); split_bf16(o1, h1, l1);
            size_t m = (size_t)(b * S_ + qbase + row) * D_ + col;
            *(__nv_bfloat162*)(g_athi + m) = __halves2bfloat162(h0, h1);
            *(__nv_bfloat162*)(g_atlo + m) = __halves2bfloat162(l0, l1);
        }
    }
}

// ------------------------- host launch ---------------------------------------
extern "C" void kernel_launch(void* const* d_in, const int* in_sizes, int n_in,
                              void* d_out, int out_size) {
    const float* x       = (const float*)d_in[0];
    const float* w_in    = (const float*)d_in[1];
    const float* b_in    = (const float*)d_in[2];
    const float* w_out   = (const float*)d_in[3];
    const float* b_out   = (const float*)d_in[4];
    const float* gate_w1 = (const float*)d_in[5];
    const float* gate_b1 = (const float*)d_in[6];
    const float* gate_w2 = (const float*)d_in[7];
    const float* gate_b2 = (const float*)d_in[8];
    float* out = (float*)d_out;

    cudaFuncSetAttribute(k_gate_qgemm, cudaFuncAttributeMaxDynamicSharedMemorySize, SMEM_GM);
    cudaFuncSetAttribute(k_topk_kv, cudaFuncAttributeMaxDynamicSharedMemorySize, SMEM_KV);
    cudaFuncSetAttribute(k_outgemm, cudaFuncAttributeMaxDynamicSharedMemorySize, SMEM_GM);
    cudaFuncSetAttribute(attn_mma, cudaFuncAttributeMaxDynamicSharedMemorySize, SMEM_AT2);

    // scale = log2(e) / sqrt(32): scores come out of QK^T in log2 domain
    const float qscale = 1.4426950408889634f * 0.17677669529663687f;

    // 1. fp32 -> bf16 hi/lo conversions (16B stores) + flag reset
    convert_all<<<(CONV_TOTAL + 255) / 256, 256>>>(
        (const float4*)x, (const float4*)w_in, (const float4*)w_out,
        (const float4*)gate_w1);

    // 2. gate GEMM (bf16x3 MMA, fused relu/dot/sigmoid) || Q projection GEMM
    k_gate_qgemm<<<GATE_BLOCKS + QG_BLOCKS, 256, SMEM_GM>>>(
        gate_b1, gate_w2, gate_b2, b_in, qscale);

    // 3. topk (4 blocks) + KV GEMM (104 blocks, B-prefetch before rowmap spin)
    k_topk_kv<<<TOPKKV_BLOCKS, 256, SMEM_KV>>>(b_in);

    // 4. attention: 2-pass QK (K as bf16), key-chunked online softmax
    attn_mma<<<dim3(B_ * H_, S_ / 64), 128, SMEM_AT2>>>();

    // 5. out projection (fp32 out)
    k_outgemm<<<dim3(D_ / 64, ROWS / 64), 256, SMEM_GM>>>(b_out, out);
}